// round 12
// baseline (speedup 1.0000x reference)
#include <cuda_runtime.h>
#include <cuda_bf16.h>
#include <cstdint>
#include <cstddef>

// Problem constants
#define DOUT 512
#define NH   8
#define HD   64
#define NQ1  256
#define NQ2  64
#define BATCH 4
#define NKEY 20000
#define DIN  256
#define LN_EPS 1e-5f
#define SCALE 0.125f
#define KSPLIT 8
#define KPER   2560

// ---------------- scratch (device globals; no allocations allowed) ----------------
__device__ float g_Q1[NQ1 * DOUT];
__device__ float g_O1[BATCH * NQ1 * DOUT];
__device__ float g_I1[BATCH * NQ1 * DOUT];
__device__ float g_Q2[NQ2 * DOUT];
__device__ float g_K2[BATCH * NQ1 * DOUT];
__device__ float g_V2[BATCH * NQ1 * DOUT];
__device__ float g_P2[BATCH * NH * NQ2 * NQ1];
__device__ float g_O2[BATCH * NQ2 * DOUT];
__device__ float g_X2[BATCH * NQ2 * DOUT];
__device__ uint4 g_Xhi[BATCH * NKEY * DIN * 2 / 16];
__device__ uint4 g_Xlo[BATCH * NKEY * DIN * 2 / 16];
__device__ uint4 g_WtKhi[DOUT * DIN * 2 / 16];
__device__ uint4 g_WtKlo[DOUT * DIN * 2 / 16];
__device__ uint4 g_WtVhi[DOUT * DIN * 2 / 16];
__device__ uint4 g_WtVlo[DOUT * DIN * 2 / 16];
__device__ uint4 g_Kh[BATCH * NKEY * DOUT * 2 / 16];
__device__ uint4 g_Kl[BATCH * NKEY * DOUT * 2 / 16];
__device__ uint4 g_Vth[(DOUT * BATCH * NKEY * 2 + 512) / 16];
__device__ uint4 g_Vtl[(DOUT * BATCH * NKEY * 2 + 512) / 16];
__device__ uint4 g_Q1h[NQ1 * DOUT * 2 / 16];
__device__ uint4 g_Q1l[NQ1 * DOUT * 2 / 16];
__device__ float g_Opart[KSPLIT * BATCH * NQ1 * DOUT];
__device__ float g_Mpart[KSPLIT * BATCH * NQ1 * NH];
__device__ float g_Lpart[KSPLIT * BATCH * NQ1 * NH];

// ---------------- helpers ------------------------------------------------------------
__device__ __forceinline__ void mma16816(float* c, const uint32_t* a, const uint32_t* b) {
    asm volatile(
        "mma.sync.aligned.m16n8k16.row.col.f32.bf16.bf16.f32 "
        "{%0,%1,%2,%3}, {%4,%5,%6,%7}, {%8,%9}, {%0,%1,%2,%3};"
        : "+f"(c[0]), "+f"(c[1]), "+f"(c[2]), "+f"(c[3])
        : "r"(a[0]), "r"(a[1]), "r"(a[2]), "r"(a[3]), "r"(b[0]), "r"(b[1]));
}
__device__ __forceinline__ void ldsm4(uint32_t* r, uint32_t addr) {
    asm volatile("ldmatrix.sync.aligned.m8n8.x4.shared.b16 {%0,%1,%2,%3}, [%4];"
        : "=r"(r[0]), "=r"(r[1]), "=r"(r[2]), "=r"(r[3]) : "r"(addr));
}
__device__ __forceinline__ uint32_t smem_u32(const void* p) {
    uint32_t a;
    asm("{ .reg .u64 t; cvta.to.shared.u64 t, %1; cvt.u32.u64 %0, t; }" : "=r"(a) : "l"(p));
    return a;
}
__device__ __forceinline__ void cp16(uint32_t dst, const void* src) {
    asm volatile("cp.async.cg.shared.global [%0], [%1], 16;" :: "r"(dst), "l"(src));
}
#define CP_COMMIT() asm volatile("cp.async.commit_group;" ::: "memory")
#define CP_WAIT1()  asm volatile("cp.async.wait_group 1;" ::: "memory")

__device__ __forceinline__ void splitpack(float f0, float f1, uint32_t& hi, uint32_t& lo) {
    __nv_bfloat16 h0 = __float2bfloat16_rn(f0);
    __nv_bfloat16 h1 = __float2bfloat16_rn(f1);
    __nv_bfloat16 e0 = __float2bfloat16_rn(f0 - __bfloat162float(h0));
    __nv_bfloat16 e1 = __float2bfloat16_rn(f1 - __bfloat162float(h1));
    hi = ((uint32_t)__bfloat16_as_ushort(h1) << 16) | (uint32_t)__bfloat16_as_ushort(h0);
    lo = ((uint32_t)__bfloat16_as_ushort(e1) << 16) | (uint32_t)__bfloat16_as_ushort(e0);
}

// ---------------- fp32 -> bf16 hi/lo split ------------------------------------------
__global__ void conv_split(const float4* __restrict__ X, uint2* __restrict__ Hi,
                           uint2* __restrict__ Lo, int n4) {
    int idx = blockIdx.x * blockDim.x + threadIdx.x;
    if (idx >= n4) return;
    float4 v = X[idx];
    uint32_t h0, l0, h1, l1;
    splitpack(v.x, v.y, h0, l0);
    splitpack(v.z, v.w, h1, l1);
    Hi[idx] = make_uint2(h0, h1);
    Lo[idx] = make_uint2(l0, l1);
}

__global__ void conv_wt(const float* __restrict__ W, __nv_bfloat16* __restrict__ Hi,
                        __nv_bfloat16* __restrict__ Lo) {
    int idx = blockIdx.x * blockDim.x + threadIdx.x;
    int n = idx >> 8, k = idx & 255;
    float w = W[k * DOUT + n];
    __nv_bfloat16 hb = __float2bfloat16_rn(w);
    Hi[idx] = hb;
    Lo[idx] = __float2bfloat16_rn(w - __bfloat162float(hb));
}

// ---------------- HMMA bf16x3 GEMM, CTA 128x64, BK=32, 2-stage cp.async -------------
// Stage layout: AHI(128x80) ALO BHI(64x80) BLO. 3 CTAs/SM target.
#define GROWB 80u
#define GA_SZ 10240u
#define GB_SZ 5120u
#define GB_OFF (2u * GA_SZ)
#define GSTG  30720u
#define SM_GEMM_TOTAL (2 * 30720)

__global__ __launch_bounds__(256, 3)
void gemm_mma_bf16x3(const uint4* __restrict__ Ahi4, const uint4* __restrict__ Alo4,
                     const uint4* __restrict__ Bhi4, const uint4* __restrict__ Blo4,
                     const float* __restrict__ bias, int bias_row,
                     __nv_bfloat16* __restrict__ Chi, __nv_bfloat16* __restrict__ Clo,
                     int ldc) {
    extern __shared__ char smc[];
    const uint32_t sbase = smem_u32(smc);
    const int tid = threadIdx.x, lane = tid & 31, w = tid >> 5;
    const int wm = w & 3, wn = w >> 2;           // warp tile 32x32: rows wm*32, cols wn*32
    const int m0 = blockIdx.y * 128, n0 = blockIdx.x * 64;

    float c[2][4][4];
#pragma unroll
    for (int mt = 0; mt < 2; mt++)
#pragma unroll
        for (int nt = 0; nt < 4; nt++)
#pragma unroll
            for (int i = 0; i < 4; i++) c[mt][nt][i] = 0.f;

    // stage loader: A = 1024 chunks, B = 512 chunks, 6 cp.async per thread
    auto load_stage = [&](int s, int kc) {
#pragma unroll
        for (int i = tid; i < 1536; i += 256) {
            uint32_t dst;
            size_t gi;
            const uint4* src;
            if (i < 1024) {
                int arr = i >> 9, rem = i & 511, r = rem >> 2, j = rem & 3;
                dst = sbase + (uint32_t)s * GSTG + (uint32_t)arr * GA_SZ
                    + (uint32_t)r * GROWB + (uint32_t)j * 16u;
                gi = (size_t)(m0 + r) * 32 + kc * 4 + j;
                src = arr ? Alo4 : Ahi4;
            } else {
                int i2 = i - 1024;
                int arr = i2 >> 8, rem = i2 & 255, r = rem >> 2, j = rem & 3;
                dst = sbase + (uint32_t)s * GSTG + GB_OFF + (uint32_t)arr * GB_SZ
                    + (uint32_t)r * GROWB + (uint32_t)j * 16u;
                gi = (size_t)(n0 + r) * 32 + kc * 4 + j;
                src = arr ? Blo4 : Bhi4;
            }
            cp16(dst, src + gi);
        }
    };

    load_stage(0, 0); CP_COMMIT();
    load_stage(1, 1); CP_COMMIT();

    for (int kc = 0; kc < 8; kc++) {
        CP_WAIT1();
        __syncthreads();
        const uint32_t sst = sbase + (uint32_t)(kc & 1) * GSTG;

#pragma unroll
        for (int ks = 0; ks < 2; ks++) {
            const uint32_t kb = (uint32_t)ks * 32u;
            uint32_t ah[2][4], al[2][4];
#pragma unroll
            for (int mt = 0; mt < 2; mt++) {
                uint32_t arow = (uint32_t)(wm * 32 + mt * 16 + (lane & 15));
                uint32_t ao = arow * GROWB + kb + (uint32_t)((lane >> 4) * 16);
                ldsm4(ah[mt], sst + ao);
                ldsm4(al[mt], sst + GA_SZ + ao);
            }
#pragma unroll
            for (int p = 0; p < 2; p++) {
                uint32_t brow = (uint32_t)(wn * 32 + p * 16 + ((lane >> 4) << 3) + (lane & 7));
                uint32_t bo = brow * GROWB + kb + (uint32_t)(((lane >> 3) & 1) * 16);
                uint32_t bh[4], bl[4];
                ldsm4(bh, sst + GB_OFF + bo);
                ldsm4(bl, sst + GB_OFF + GB_SZ + bo);
#pragma unroll
                for (int half = 0; half < 2; half++)
#pragma unroll
                    for (int mt = 0; mt < 2; mt++)
                        mma16816(c[mt][2 * p + half], ah[mt], bh + 2 * half);
#pragma unroll
                for (int half = 0; half < 2; half++)
#pragma unroll
                    for (int mt = 0; mt < 2; mt++)
                        mma16816(c[mt][2 * p + half], ah[mt], bl + 2 * half);
#pragma unroll
                for (int half = 0; half < 2; half++)
#pragma unroll
                    for (int mt = 0; mt < 2; mt++)
                        mma16816(c[mt][2 * p + half], al[mt], bh + 2 * half);
            }
        }
        __syncthreads();
        if (kc + 2 < 8) load_stage(kc & 1, kc + 2);
        CP_COMMIT();
    }

#pragma unroll
    for (int mt = 0; mt < 2; mt++) {
        int row = m0 + wm * 32 + mt * 16 + (lane >> 2);
#pragma unroll
        for (int nt = 0; nt < 4; nt++) {
            int col = n0 + wn * 32 + nt * 8 + (lane & 3) * 2;
            float v0, v1, v2, v3;
            if (bias_row) {
                float br0 = bias[row], br1 = bias[row + 8];
                v0 = c[mt][nt][0] + br0; v1 = c[mt][nt][1] + br0;
                v2 = c[mt][nt][2] + br1; v3 = c[mt][nt][3] + br1;
            } else {
                float bc0 = bias[col], bc1 = bias[col + 1];
                v0 = c[mt][nt][0] + bc0; v1 = c[mt][nt][1] + bc1;
                v2 = c[mt][nt][2] + bc0; v3 = c[mt][nt][3] + bc1;
            }
            uint32_t h01, l01, h23, l23;
            splitpack(v0, v1, h01, l01);
            splitpack(v2, v3, h23, l23);
            *(uint32_t*)(Chi + (size_t)row * ldc + col) = h01;
            *(uint32_t*)(Clo + (size_t)row * ldc + col) = l01;
            *(uint32_t*)(Chi + (size_t)(row + 8) * ldc + col) = h23;
            *(uint32_t*)(Clo + (size_t)(row + 8) * ldc + col) = l23;
        }
    }
}

// ---------------- generic tiled SGEMM (small fp32 matrices) -------------------------
__global__ void sgemm_bias(const float* __restrict__ A, const float* __restrict__ B,
                           const float* __restrict__ bias, float* __restrict__ C,
                           int M, int N, int K) {
    __shared__ float As[16][68];
    __shared__ float Bs[16][68];
    const int tid = threadIdx.x;
    const int tn = tid & 15, tm = tid >> 4;
    const int m0 = blockIdx.y * 64, n0 = blockIdx.x * 64;

    float acc[4][4];
#pragma unroll
    for (int i = 0; i < 4; i++)
#pragma unroll
        for (int j = 0; j < 4; j++) acc[i][j] = 0.f;

    for (int k0 = 0; k0 < K; k0 += 16) {
        {
            int m = tid >> 2;
            int kq = (tid & 3) * 4;
            float4 v = *(const float4*)(A + (size_t)(m0 + m) * K + k0 + kq);
            As[kq + 0][m] = v.x; As[kq + 1][m] = v.y;
            As[kq + 2][m] = v.z; As[kq + 3][m] = v.w;
        }
        {
            int kk = tid >> 4;
            int nq = (tid & 15) * 4;
            *(float4*)&Bs[kk][nq] = *(const float4*)(B + (size_t)(k0 + kk) * N + n0 + nq);
        }
        __syncthreads();
#pragma unroll
        for (int kk = 0; kk < 16; kk++) {
            float4 a = *(const float4*)&As[kk][tm * 4];
            float4 b = *(const float4*)&Bs[kk][tn * 4];
            float av[4] = {a.x, a.y, a.z, a.w};
            float bv[4] = {b.x, b.y, b.z, b.w};
#pragma unroll
            for (int i = 0; i < 4; i++)
#pragma unroll
                for (int j = 0; j < 4; j++) acc[i][j] += av[i] * bv[j];
        }
        __syncthreads();
    }
#pragma unroll
    for (int i = 0; i < 4; i++) {
        size_t m = (size_t)(m0 + tm * 4 + i);
#pragma unroll
        for (int j = 0; j < 4; j++) {
            int n = n0 + tn * 4 + j;
            C[m * N + n] = acc[i][j] + bias[n];
        }
    }
}

// ---------------- Q1 fp32 -> bf16 hi/lo ---------------------------------------------
__global__ void q_split(const float* __restrict__ Q, __nv_bfloat16* __restrict__ Qh,
                        __nv_bfloat16* __restrict__ Ql, int n) {
    int idx = blockIdx.x * blockDim.x + threadIdx.x;
    if (idx >= n) return;
    float v = Q[idx];
    __nv_bfloat16 hb = __float2bfloat16_rn(v);
    Qh[idx] = hb;
    Ql[idx] = __float2bfloat16_rn(v - __bfloat162float(hb));
}

// ---------------- tensor-core flash attention, stage 1, key-split -------------------
#define FL_RB  144
#define FL_QH 0
#define FL_QL 9216
#define FL_KH 18432
#define FL_KL 27648
#define FL_VH 36864
#define FL_VL 46080
#define FL_MK 55296
#define FL_SMEM (55296 + 256)

__global__ __launch_bounds__(128)
void flash1_tc(const __nv_bfloat16* __restrict__ Qh, const __nv_bfloat16* __restrict__ Ql,
               const __nv_bfloat16* __restrict__ Kh, const __nv_bfloat16* __restrict__ Kl,
               const __nv_bfloat16* __restrict__ Vth, const __nv_bfloat16* __restrict__ Vtl,
               const int* __restrict__ mask,
               float* __restrict__ Op, float* __restrict__ Mp, float* __restrict__ Lp) {
    extern __shared__ char sb[];
    const uint32_t fb = smem_u32(sb);
    float* mk = (float*)(sb + FL_MK);
    const int tid = threadIdx.x, lane = tid & 31, w = tid >> 5;
    const int qt = blockIdx.x & 3, ks = blockIdx.x >> 2;
    const int h = blockIdx.y, b = blockIdx.z;
    const int k_begin = ks * KPER;
    const int k_end = min(k_begin + KPER, NKEY);

    for (int idx = tid; idx < 512; idx += 128) {
        int row = idx >> 3, j = idx & 7;
        size_t g = (size_t)(qt * 64 + row) * DOUT + h * HD + j * 8;
        *(uint4*)(sb + FL_QH + row * FL_RB + j * 16) = *(const uint4*)(Qh + g);
        *(uint4*)(sb + FL_QL + row * FL_RB + j * 16) = *(const uint4*)(Ql + g);
    }
    __syncthreads();

    uint32_t qfh[4][4], qfl[4][4];
    {
        uint32_t base = (uint32_t)(w * 16 + (lane >> 2)) * FL_RB + (lane & 3) * 4;
#pragma unroll
        for (int kd = 0; kd < 4; kd++) {
            uint32_t o0 = base + kd * 32;
            qfh[kd][0] = *(const uint32_t*)(sb + FL_QH + o0);
            qfh[kd][1] = *(const uint32_t*)(sb + FL_QH + o0 + 8 * FL_RB);
            qfh[kd][2] = *(const uint32_t*)(sb + FL_QH + o0 + 16);
            qfh[kd][3] = *(const uint32_t*)(sb + FL_QH + o0 + 8 * FL_RB + 16);
            qfl[kd][0] = *(const uint32_t*)(sb + FL_QL + o0);
            qfl[kd][1] = *(const uint32_t*)(sb + FL_QL + o0 + 8 * FL_RB);
            qfl[kd][2] = *(const uint32_t*)(sb + FL_QL + o0 + 16);
            qfl[kd][3] = *(const uint32_t*)(sb + FL_QL + o0 + 8 * FL_RB + 16);
        }
    }

    float m0 = -1e30f, m1 = -1e30f, lsum0 = 0.f, lsum1 = 0.f;
    float o[8][4];
#pragma unroll
    for (int nt = 0; nt < 8; nt++)
#pragma unroll
        for (int i = 0; i < 4; i++) o[nt][i] = 0.f;

    const uint32_t brow_lane = (uint32_t)(((lane >> 4) << 3) + (lane & 7));
    const uint32_t bcol16 = (uint32_t)(((lane >> 3) & 1) * 16);

    for (int kc = k_begin; kc < k_end; kc += 64) {
        int rem = min(64, k_end - kc);
        int pm = 0;
        if (tid < 64) {
            pm = (tid >= rem) || (mask[(size_t)b * NKEY + kc + tid] != 0);
            mk[tid] = pm ? 1.f : 0.f;
        }
        if (__syncthreads_count(pm) == 64) continue;

        for (int idx = tid; idx < 512; idx += 128) {
            int row = idx >> 3, j = idx & 7;
            uint4 zh = make_uint4(0, 0, 0, 0), zl = zh;
            if (row < rem) {
                size_t g = (size_t)(b * NKEY + kc + row) * DOUT + h * HD + j * 8;
                zh = *(const uint4*)(Kh + g);
                zl = *(const uint4*)(Kl + g);
            }
            *(uint4*)(sb + FL_KH + row * FL_RB + j * 16) = zh;
            *(uint4*)(sb + FL_KL + row * FL_RB + j * 16) = zl;
            size_t gv = (size_t)(h * HD + row) * (BATCH * NKEY) + (size_t)b * NKEY + kc + j * 8;
            *(uint4*)(sb + FL_VH + row * FL_RB + j * 16) = *(const uint4*)(Vth + gv);
            *(uint4*)(sb + FL_VL + row * FL_RB + j * 16) = *(const uint4*)(Vtl + gv);
        }
        __syncthreads();

        // ---- S = Q K^T (bf16x3), term-pass ordered ----
        float s[8][4];
#pragma unroll
        for (int nt = 0; nt < 8; nt++)
#pragma unroll
            for (int i = 0; i < 4; i++) s[nt][i] = 0.f;
#pragma unroll
        for (int kd = 0; kd < 4; kd++) {
            uint32_t cb = kd * 32 + bcol16;
#pragma unroll
            for (int pp = 0; pp < 2; pp++) {
                uint32_t bo0 = ((uint32_t)((2 * pp) * 16) + brow_lane) * FL_RB + cb;
                uint32_t bo1 = ((uint32_t)((2 * pp + 1) * 16) + brow_lane) * FL_RB + cb;
                uint32_t bh0[4], bl0[4], bh1[4], bl1[4];
                ldsm4(bh0, fb + FL_KH + bo0);
                ldsm4(bl0, fb + FL_KL + bo0);
                ldsm4(bh1, fb + FL_KH + bo1);
                ldsm4(bl1, fb + FL_KL + bo1);
                float* s0 = s[4 * pp + 0];
                float* s1 = s[4 * pp + 1];
                float* s2 = s[4 * pp + 2];
                float* s3 = s[4 * pp + 3];
                mma16816(s0, qfh[kd], bh0);
                mma16816(s1, qfh[kd], bh0 + 2);
                mma16816(s2, qfh[kd], bh1);
                mma16816(s3, qfh[kd], bh1 + 2);
                mma16816(s0, qfh[kd], bl0);
                mma16816(s1, qfh[kd], bl0 + 2);
                mma16816(s2, qfh[kd], bl1);
                mma16816(s3, qfh[kd], bl1 + 2);
                mma16816(s0, qfl[kd], bh0);
                mma16816(s1, qfl[kd], bh0 + 2);
                mma16816(s2, qfl[kd], bh1);
                mma16816(s3, qfl[kd], bh1 + 2);
            }
        }

        // ---- mask + scale + online softmax ----
        float mx0 = -1e30f, mx1 = -1e30f;
#pragma unroll
        for (int nt = 0; nt < 8; nt++) {
            int c0 = nt * 8 + (lane & 3) * 2;
            float2 mm = *(const float2*)&mk[c0];
            s[nt][0] = (mm.x > 0.f) ? -1e30f : s[nt][0] * SCALE;
            s[nt][1] = (mm.y > 0.f) ? -1e30f : s[nt][1] * SCALE;
            s[nt][2] = (mm.x > 0.f) ? -1e30f : s[nt][2] * SCALE;
            s[nt][3] = (mm.y > 0.f) ? -1e30f : s[nt][3] * SCALE;
            mx0 = fmaxf(mx0, fmaxf(s[nt][0], s[nt][1]));
            mx1 = fmaxf(mx1, fmaxf(s[nt][2], s[nt][3]));
        }
        mx0 = fmaxf(mx0, __shfl_xor_sync(0xffffffffu, mx0, 1));
        mx0 = fmaxf(mx0, __shfl_xor_sync(0xffffffffu, mx0, 2));
        mx1 = fmaxf(mx1, __shfl_xor_sync(0xffffffffu, mx1, 1));
        mx1 = fmaxf(mx1, __shfl_xor_sync(0xffffffffu, mx1, 2));
        float mn0 = fmaxf(m0, mx0), mn1 = fmaxf(m1, mx1);
        float a0 = __expf(m0 - mn0), a1 = __expf(m1 - mn1);
        m0 = mn0; m1 = mn1;
        float rs0 = 0.f, rs1 = 0.f;
#pragma unroll
        for (int nt = 0; nt < 8; nt++) {
            s[nt][0] = __expf(s[nt][0] - mn0);
            s[nt][1] = __expf(s[nt][1] - mn0);
            s[nt][2] = __expf(s[nt][2] - mn1);
            s[nt][3] = __expf(s[nt][3] - mn1);
            rs0 += s[nt][0] + s[nt][1];
            rs1 += s[nt][2] + s[nt][3];
        }
        rs0 += __shfl_xor_sync(0xffffffffu, rs0, 1);
        rs0 += __shfl_xor_sync(0xffffffffu, rs0, 2);
        rs1 += __shfl_xor_sync(0xffffffffu, rs1, 1);
        rs1 += __shfl_xor_sync(0xffffffffu, rs1, 2);
        lsum0 = lsum0 * a0 + rs0;
        lsum1 = lsum1 * a1 + rs1;
#pragma unroll
        for (int nt = 0; nt < 8; nt++) {
            o[nt][0] *= a0; o[nt][1] *= a0; o[nt][2] *= a1; o[nt][3] *= a1;
        }

        // ---- O += P V (bf16x3), term-pass ordered ----
#pragma unroll
        for (int k2 = 0; k2 < 4; k2++) {
            uint32_t aph[4], apl[4];
            splitpack(s[2 * k2][0],     s[2 * k2][1],     aph[0], apl[0]);
            splitpack(s[2 * k2][2],     s[2 * k2][3],     aph[1], apl[1]);
            splitpack(s[2 * k2 + 1][0], s[2 * k2 + 1][1], aph[2], apl[2]);
            splitpack(s[2 * k2 + 1][2], s[2 * k2 + 1][3], aph[3], apl[3]);
            uint32_t cb = k2 * 32 + bcol16;
#pragma unroll
            for (int pp = 0; pp < 2; pp++) {
                uint32_t vo0 = ((uint32_t)((2 * pp) * 16) + brow_lane) * FL_RB + cb;
                uint32_t vo1 = ((uint32_t)((2 * pp + 1) * 16) + brow_lane) * FL_RB + cb;
                uint32_t vh0[4], vl0[4], vh1[4], vl1[4];
                ldsm4(vh0, fb + FL_VH + vo0);
                ldsm4(vl0, fb + FL_VL + vo0);
                ldsm4(vh1, fb + FL_VH + vo1);
                ldsm4(vl1, fb + FL_VL + vo1);
                float* o0 = o[4 * pp + 0];
                float* o1 = o[4 * pp + 1];
                float* o2 = o[4 * pp + 2];
                float* o3 = o[4 * pp + 3];
                mma16816(o0, aph, vh0);
                mma16816(o1, aph, vh0 + 2);
                mma16816(o2, aph, vh1);
                mma16816(o3, aph, vh1 + 2);
                mma16816(o0, aph, vl0);
                mma16816(o1, aph, vl0 + 2);
                mma16816(o2, aph, vl1);
                mma16816(o3, aph, vl1 + 2);
                mma16816(o0, apl, vh0);
                mma16816(o1, apl, vh0 + 2);
                mma16816(o2, apl, vh1);
                mma16816(o3, apl, vh1 + 2);
            }
        }
    }

    {
        int r = w * 16 + (lane >> 2);
        int q0 = qt * 64 + r, q1 = q0 + 8;
        size_t ob = ((size_t)ks * BATCH + b) * NQ1;
#pragma unroll
        for (int nt = 0; nt < 8; nt++) {
            int col = h * HD + nt * 8 + (lane & 3) * 2;
            *(float2*)&Op[(ob + q0) * DOUT + col] = make_float2(o[nt][0], o[nt][1]);
            *(float2*)&Op[(ob + q1) * DOUT + col] = make_float2(o[nt][2], o[nt][3]);
        }
        if ((lane & 3) == 0) {
            size_t mi0 = (ob + q0) * NH + h, mi1 = (ob + q1) * NH + h;
            Mp[mi0] = m0; Lp[mi0] = lsum0;
            Mp[mi1] = m1; Lp[mi1] = lsum1;
        }
    }
}

// ---------------- merge key-split partials ------------------------------------------
__global__ void flash_merge(const float* __restrict__ Op, const float* __restrict__ Mp,
                            const float* __restrict__ Lp, float* __restrict__ O) {
    const int q = blockIdx.x, h = blockIdx.y, b = blockIdx.z;
    const int tid = threadIdx.x;   // 64
    __shared__ float sm_[KSPLIT], sl_[KSPLIT];
    if (tid < KSPLIT) {
        size_t mi = (((size_t)tid * BATCH + b) * NQ1 + q) * NH + h;
        sm_[tid] = Mp[mi];
        sl_[tid] = Lp[mi];
    }
    __syncthreads();
    float M = sm_[0];
#pragma unroll
    for (int s = 1; s < KSPLIT; s++) M = fmaxf(M, sm_[s]);
    float num = 0.f, den = 0.f;
#pragma unroll
    for (int s = 0; s < KSPLIT; s++) {
        float w = __expf(sm_[s] - M);
        den += w * sl_[s];
        num += w * Op[(((size_t)s * BATCH + b) * NQ1 + q) * DOUT + h * HD + tid];
    }
    O[((size_t)(b * NQ1) + q) * DOUT + h * HD + tid] = num / den;
}

// ---------------- stage-2 attention -------------------------------------------------
__global__ void attn2_kernel(const float* __restrict__ Q2, const float* __restrict__ K2,
                             const float* __restrict__ V2, float* __restrict__ P,
                             float* __restrict__ O2) {
    const int q = blockIdx.x, h = blockIdx.y, b = blockIdx.z;
    __shared__ float qs[HD];
    __shared__ float ps[NQ1];
    __shared__ float red[4];
    const int tid = threadIdx.x;   // 128

    if (tid < HD) qs[tid] = Q2[(size_t)q * DOUT + h * HD + tid];
    __syncthreads();

    float sv[2];
#pragma unroll
    for (int r = 0; r < 2; r++) {
        int k = tid + r * 128;
        const float* kr = K2 + ((size_t)(b * NQ1 + k)) * DOUT + h * HD;
        float s = 0.f;
#pragma unroll 8
        for (int d = 0; d < HD; d++) s += qs[d] * kr[d];
        sv[r] = s * SCALE;
    }
    float mx = fmaxf(sv[0], sv[1]);
#pragma unroll
    for (int off = 16; off > 0; off >>= 1) mx = fmaxf(mx, __shfl_xor_sync(0xffffffffu, mx, off));
    if ((tid & 31) == 0) red[tid >> 5] = mx;
    __syncthreads();
    mx = fmaxf(fmaxf(red[0], red[1]), fmaxf(red[2], red[3]));

    float e0 = __expf(sv[0] - mx), e1 = __expf(sv[1] - mx);
    float sum = e0 + e1;
#pragma unroll
    for (int off = 16; off > 0; off >>= 1) sum += __shfl_xor_sync(0xffffffffu, sum, off);
    __syncthreads();
    if ((tid & 31) == 0) red[tid >> 5] = sum;
    __syncthreads();
    sum = red[0] + red[1] + red[2] + red[3];
    float inv = 1.f / sum;

    ps[tid] = e0 * inv; ps[tid + 128] = e1 * inv;
    float* Prow = P + (((size_t)(b * NH + h) * NQ2 + q) * NQ1);
    Prow[tid] = e0 * inv; Prow[tid + 128] = e1 * inv;
    __syncthreads();

    if (tid < HD) {
        float acc = 0.f;
        for (int k = 0; k < NQ1; k++)
            acc += ps[k] * V2[((size_t)(b * NQ1 + k)) * DOUT + h * HD + tid];
        O2[((size_t)(b * NQ2 + q)) * DOUT + h * HD + tid] = acc;
    }
}

__global__ void attn_mean_kernel(const float* __restrict__ P, float* __restrict__ out) {
    int idx = blockIdx.x * blockDim.x + threadIdx.x;
    if (idx >= BATCH * NQ2 * NQ1) return;
    int k = idx % NQ1;
    int q = (idx / NQ1) % NQ2;
    int b = idx / (NQ1 * NQ2);
    float s = 0.f;
#pragma unroll
    for (int h = 0; h < NH; h++)
        s += P[(((size_t)(b * NH + h) * NQ2) + q) * NQ1 + k];
    out[idx] = s * (1.f / NH);
}

__global__ void ln_kernel(const float* __restrict__ X, const float* __restrict__ g,
                          const float* __restrict__ be, float* __restrict__ Y) {
    const int row = blockIdx.x;
    const float* x = X + (size_t)row * DOUT;
    float* y = Y + (size_t)row * DOUT;
    const int tid = threadIdx.x;   // 128
    float s = 0.f, s2 = 0.f;
#pragma unroll
    for (int i = tid; i < DOUT; i += 128) { float v = x[i]; s += v; s2 += v * v; }
    __shared__ float rs[4], rs2[4];
#pragma unroll
    for (int off = 16; off > 0; off >>= 1) {
        s  += __shfl_xor_sync(0xffffffffu, s,  off);
        s2 += __shfl_xor_sync(0xffffffffu, s2, off);
    }
    if ((tid & 31) == 0) { rs[tid >> 5] = s; rs2[tid >> 5] = s2; }
    __syncthreads();
    s  = rs[0]  + rs[1]  + rs[2]  + rs[3];
    s2 = rs2[0] + rs2[1] + rs2[2] + rs2[3];
    float mu  = s * (1.f / DOUT);
    float var = s2 * (1.f / DOUT) - mu * mu;
    float inv = rsqrtf(var + LN_EPS);
#pragma unroll
    for (int i = tid; i < DOUT; i += 128)
        y[i] = (x[i] - mu) * inv * g[i] + be[i];
}

// ---------------- host ----------------------------------------------------------------
extern "C" void kernel_launch(void* const* d_in, const int* in_sizes, int n_in,
                              void* d_out, int out_size) {
    const float* X    = (const float*)d_in[0];
    const int*   mask = (const int*)d_in[1];
    const float* q1   = (const float*)d_in[2];
    const float* Wq1  = (const float*)d_in[3];
    const float* bq1  = (const float*)d_in[4];
    const float* Wk1  = (const float*)d_in[5];
    const float* bk1  = (const float*)d_in[6];
    const float* Wv1  = (const float*)d_in[7];
    const float* bv1  = (const float*)d_in[8];
    const float* Wo1  = (const float*)d_in[9];
    const float* bo1  = (const float*)d_in[10];
    const float* g1   = (const float*)d_in[11];
    const float* be1  = (const float*)d_in[12];
    const float* q2   = (const float*)d_in[13];
    const float* Wq2  = (const float*)d_in[14];
    const float* bq2  = (const float*)d_in[15];
    const float* Wk2  = (const float*)d_in[16];
    const float* bk2  = (const float*)d_in[17];
    const float* Wv2  = (const float*)d_in[18];
    const float* bv2  = (const float*)d_in[19];
    const float* Wo2  = (const float*)d_in[20];
    const float* bo2  = (const float*)d_in[21];
    const float* g2   = (const float*)d_in[22];
    const float* be2  = (const float*)d_in[23];

    float* out = (float*)d_out;
    float* out_attn = out + BATCH * NQ2 * DOUT;

    float *Q1, *O1, *I1, *Q2, *K2, *V2, *P2, *O2, *X2, *Opart, *Mpart, *Lpart;
    uint4 *Xhi, *Xlo, *WtKhi, *WtKlo, *WtVhi, *WtVlo, *Kh, *Kl, *Vth, *Vtl, *Q1h, *Q1l;
    cudaGetSymbolAddress((void**)&Q1, g_Q1);
    cudaGetSymbolAddress((void**)&O1, g_O1);
    cudaGetSymbolAddress((void**)&I1, g_I1);
    cudaGetSymbolAddress((void**)&Q2, g_Q2);
    cudaGetSymbolAddress((void**)&K2, g_K2);
    cudaGetSymbolAddress((void**)&V2, g_V2);
    cudaGetSymbolAddress((void**)&P2, g_P2);
    cudaGetSymbolAddress((void**)&O2, g_O2);
    cudaGetSymbolAddress((void**)&X2, g_X2);
    cudaGetSymbolAddress((void**)&Opart, g_Opart);
    cudaGetSymbolAddress((void**)&Mpart, g_Mpart);
    cudaGetSymbolAddress((void**)&Lpart, g_Lpart);
    cudaGetSymbolAddress((void**)&Xhi, g_Xhi);
    cudaGetSymbolAddress((void**)&Xlo, g_Xlo);
    cudaGetSymbolAddress((void**)&WtKhi, g_WtKhi);
    cudaGetSymbolAddress((void**)&WtKlo, g_WtKlo);
    cudaGetSymbolAddress((void**)&WtVhi, g_WtVhi);
    cudaGetSymbolAddress((void**)&WtVlo, g_WtVlo);
    cudaGetSymbolAddress((void**)&Kh, g_Kh);
    cudaGetSymbolAddress((void**)&Kl, g_Kl);
    cudaGetSymbolAddress((void**)&Vth, g_Vth);
    cudaGetSymbolAddress((void**)&Vtl, g_Vtl);
    cudaGetSymbolAddress((void**)&Q1h, g_Q1h);
    cudaGetSymbolAddress((void**)&Q1l, g_Q1l);

    cudaFuncSetAttribute(gemm_mma_bf16x3, cudaFuncAttributeMaxDynamicSharedMemorySize, SM_GEMM_TOTAL);
    cudaFuncSetAttribute(flash1_tc, cudaFuncAttributeMaxDynamicSharedMemorySize, FL_SMEM);

    // ---- stage 1 ----
    const int n4 = BATCH * NKEY * DIN / 4;
    conv_split<<<(n4 + 255) / 256, 256>>>((const float4*)X, (uint2*)Xhi, (uint2*)Xlo, n4);
    conv_wt<<<(DOUT * DIN) / 256, 256>>>(Wk1, (__nv_bfloat16*)WtKhi, (__nv_bfloat16*)WtKlo);
    conv_wt<<<(DOUT * DIN) / 256, 256>>>(Wv1, (__nv_bfloat16*)WtVhi, (__nv_bfloat16*)WtVlo);

    // K[token][d] = X @ WtK^T + bk1(col): M = 80000, N = 512
    gemm_mma_bf16x3<<<dim3(8, BATCH * NKEY / 128), 256, SM_GEMM_TOTAL>>>(
        Xhi, Xlo, WtKhi, WtKlo, bk1, 0,
        (__nv_bfloat16*)Kh, (__nv_bfloat16*)Kl, DOUT);
    // Vt[d][token] = WtV @ X^T + bv1(row): M = 512, N = 80000
    gemm_mma_bf16x3<<<dim3(BATCH * NKEY / 64, 4), 256, SM_GEMM_TOTAL>>>(
        WtVhi, WtVlo, Xhi, Xlo, bv1, 1,
        (__nv_bfloat16*)Vth, (__nv_bfloat16*)Vtl, BATCH * NKEY);

    sgemm_bias<<<dim3(8, 4), 256>>>(q1, Wq1, bq1, Q1, NQ1, DOUT, DOUT);
    q_split<<<(NQ1 * DOUT + 255) / 256, 256>>>(Q1, (__nv_bfloat16*)Q1h, (__nv_bfloat16*)Q1l, NQ1 * DOUT);

    flash1_tc<<<dim3(4 * KSPLIT, NH, BATCH), 128, FL_SMEM>>>(
        (const __nv_bfloat16*)Q1h, (const __nv_bfloat16*)Q1l,
        (const __nv_bfloat16*)Kh, (const __nv_bfloat16*)Kl,
        (const __nv_bfloat16*)Vth, (const __nv_bfloat16*)Vtl,
        mask, Opart, Mpart, Lpart);
    flash_merge<<<dim3(NQ1, NH, BATCH), 64>>>(Opart, Mpart, Lpart, O1);

    sgemm_bias<<<dim3(8, 16), 256>>>(O1, Wo1, bo1, I1, BATCH * NQ1, DOUT, DOUT);
    ln_kernel<<<BATCH * NQ1, 128>>>(I1, g1, be1, I1);

    // ---- stage 2 ----
    sgemm_bias<<<dim3(8, 1),  256>>>(q2, Wq2, bq2, Q2, NQ2, DOUT, DOUT);
    sgemm_bias<<<dim3(8, 16), 256>>>(I1, Wk2, bk2, K2, BATCH * NQ1, DOUT, DOUT);
    sgemm_bias<<<dim3(8, 16), 256>>>(I1, Wv2, bv2, V2, BATCH * NQ1, DOUT, DOUT);
    attn2_kernel<<<dim3(NQ2, NH, BATCH), 128>>>(Q2, K2, V2, P2, O2);
    attn_mean_kernel<<<(BATCH * NQ2 * NQ1 + 255) / 256, 256>>>(P2, out_attn);
    sgemm_bias<<<dim3(8, 4), 256>>>(O2, Wo2, bo2, X2, NQ2 * BATCH, DOUT, DOUT);
    ln_kernel<<<BATCH * NQ2, 128>>>(X2, g2, be2, out);
}

// round 13
// speedup vs baseline: 1.4465x; 1.4465x over previous
#include <cuda_runtime.h>
#include <cuda_fp16.h>
#include <cstdint>
#include <cstddef>

// Problem constants
#define DOUT 512
#define NH   8
#define HD   64
#define NQ1  256
#define NQ2  64
#define BATCH 4
#define NKEY 20000
#define DIN  256
#define LN_EPS 1e-5f
#define SCALE 0.125f
#define KSPLIT 8
#define KPER   2560

// ---------------- scratch (device globals; no allocations allowed) ----------------
__device__ float g_Q1[NQ1 * DOUT];
__device__ float g_O1[BATCH * NQ1 * DOUT];
__device__ float g_I1[BATCH * NQ1 * DOUT];
__device__ float g_Q2[NQ2 * DOUT];
__device__ float g_K2[BATCH * NQ1 * DOUT];
__device__ float g_V2[BATCH * NQ1 * DOUT];
__device__ float g_P2[BATCH * NH * NQ2 * NQ1];
__device__ float g_O2[BATCH * NQ2 * DOUT];
__device__ float g_X2[BATCH * NQ2 * DOUT];
__device__ uint4 g_Xh[BATCH * NKEY * DIN * 2 / 16];     // fp16
__device__ uint4 g_WtK[DOUT * DIN * 2 / 16];            // fp16 [512][256]
__device__ uint4 g_WtV[DOUT * DIN * 2 / 16];
__device__ uint4 g_K16[BATCH * NKEY * DOUT * 2 / 16];   // fp16 K [token][d]
__device__ uint4 g_Vt16[(DOUT * BATCH * NKEY * 2 + 512) / 16]; // fp16 V [d][token]
__device__ uint4 g_Q1h[NQ1 * DOUT * 2 / 16];
__device__ float g_Opart[KSPLIT * BATCH * NQ1 * DOUT];
__device__ float g_Mpart[KSPLIT * BATCH * NQ1 * NH];
__device__ float g_Lpart[KSPLIT * BATCH * NQ1 * NH];

// ---------------- helpers ------------------------------------------------------------
__device__ __forceinline__ void mma_f16(float* c, const uint32_t* a, const uint32_t* b) {
    asm volatile(
        "mma.sync.aligned.m16n8k16.row.col.f32.f16.f16.f32 "
        "{%0,%1,%2,%3}, {%4,%5,%6,%7}, {%8,%9}, {%0,%1,%2,%3};"
        : "+f"(c[0]), "+f"(c[1]), "+f"(c[2]), "+f"(c[3])
        : "r"(a[0]), "r"(a[1]), "r"(a[2]), "r"(a[3]), "r"(b[0]), "r"(b[1]));
}
__device__ __forceinline__ void ldsm4(uint32_t* r, uint32_t addr) {
    asm volatile("ldmatrix.sync.aligned.m8n8.x4.shared.b16 {%0,%1,%2,%3}, [%4];"
        : "=r"(r[0]), "=r"(r[1]), "=r"(r[2]), "=r"(r[3]) : "r"(addr));
}
__device__ __forceinline__ uint32_t smem_u32(const void* p) {
    uint32_t a;
    asm("{ .reg .u64 t; cvta.to.shared.u64 t, %1; cvt.u32.u64 %0, t; }" : "=r"(a) : "l"(p));
    return a;
}
__device__ __forceinline__ void cp16(uint32_t dst, const void* src) {
    asm volatile("cp.async.cg.shared.global [%0], [%1], 16;" :: "r"(dst), "l"(src));
}
#define CP_COMMIT() asm volatile("cp.async.commit_group;" ::: "memory")
#define CP_WAIT1()  asm volatile("cp.async.wait_group 1;" ::: "memory")

__device__ __forceinline__ uint32_t packh2(float f0, float f1) {
    __half2 h = __floats2half2_rn(f0, f1);
    return *(uint32_t*)&h;
}

// ---------------- fp32 -> fp16 conversions ------------------------------------------
__global__ void conv_half(const float4* __restrict__ X, uint2* __restrict__ H, int n4) {
    int idx = blockIdx.x * blockDim.x + threadIdx.x;
    if (idx >= n4) return;
    float4 v = X[idx];
    H[idx] = make_uint2(packh2(v.x, v.y), packh2(v.z, v.w));
}

// W[K=256,N=512] -> Wt[N=512,K=256] fp16
__global__ void conv_wt_h(const float* __restrict__ W, __half* __restrict__ Wt) {
    int idx = blockIdx.x * blockDim.x + threadIdx.x;
    int n = idx >> 8, k = idx & 255;
    Wt[idx] = __float2half_rn(W[k * DOUT + n]);
}

__global__ void q_half(const float* __restrict__ Q, __half* __restrict__ Qh, int n) {
    int idx = blockIdx.x * blockDim.x + threadIdx.x;
    if (idx >= n) return;
    Qh[idx] = __float2half_rn(Q[idx]);
}

// ---------------- HMMA fp16 GEMM: C = A@B^T + bias, fp16 output ---------------------
// CTA 128x64, BK=32, 2-stage cp.async. A fp16 [M,256], B fp16 [N,256] K-major.
#define GROWB 80u
#define GA_SZ 10240u
#define GB_OFF 10240u
#define GSTG  15360u
#define SM_GEMM_TOTAL (2 * 15360)

__global__ __launch_bounds__(256, 3)
void gemm_mma_fp16(const uint4* __restrict__ Ah4, const uint4* __restrict__ Bh4,
                   const float* __restrict__ bias, int bias_row,
                   __half* __restrict__ Ch, int ldc) {
    extern __shared__ char smc[];
    const uint32_t sbase = smem_u32(smc);
    const int tid = threadIdx.x, lane = tid & 31, w = tid >> 5;
    const int wm = w & 3, wn = w >> 2;           // warp tile 32x32
    const int m0 = blockIdx.y * 128, n0 = blockIdx.x * 64;

    float c[2][4][4];
#pragma unroll
    for (int mt = 0; mt < 2; mt++)
#pragma unroll
        for (int nt = 0; nt < 4; nt++)
#pragma unroll
            for (int i = 0; i < 4; i++) c[mt][nt][i] = 0.f;

    // stage loader: A 512 chunks + B 256 chunks = 768, 3 per thread
    auto load_stage = [&](int s, int kc) {
#pragma unroll
        for (int i = tid; i < 768; i += 256) {
            uint32_t dst;
            size_t gi;
            const uint4* src;
            if (i < 512) {
                int r = i >> 2, j = i & 3;
                dst = sbase + (uint32_t)s * GSTG + (uint32_t)r * GROWB + (uint32_t)j * 16u;
                gi = (size_t)(m0 + r) * 32 + kc * 4 + j;
                src = Ah4;
            } else {
                int i2 = i - 512;
                int r = i2 >> 2, j = i2 & 3;
                dst = sbase + (uint32_t)s * GSTG + GB_OFF + (uint32_t)r * GROWB + (uint32_t)j * 16u;
                gi = (size_t)(n0 + r) * 32 + kc * 4 + j;
                src = Bh4;
            }
            cp16(dst, src + gi);
        }
    };

    load_stage(0, 0); CP_COMMIT();
    load_stage(1, 1); CP_COMMIT();

    for (int kc = 0; kc < 8; kc++) {
        CP_WAIT1();
        __syncthreads();
        const uint32_t sst = sbase + (uint32_t)(kc & 1) * GSTG;

#pragma unroll
        for (int ks = 0; ks < 2; ks++) {
            const uint32_t kb = (uint32_t)ks * 32u;
            uint32_t ah[2][4];
#pragma unroll
            for (int mt = 0; mt < 2; mt++) {
                uint32_t arow = (uint32_t)(wm * 32 + mt * 16 + (lane & 15));
                uint32_t ao = arow * GROWB + kb + (uint32_t)((lane >> 4) * 16);
                ldsm4(ah[mt], sst + ao);
            }
#pragma unroll
            for (int p = 0; p < 2; p++) {
                uint32_t brow = (uint32_t)(wn * 32 + p * 16 + ((lane >> 4) << 3) + (lane & 7));
                uint32_t bo = brow * GROWB + kb + (uint32_t)(((lane >> 3) & 1) * 16);
                uint32_t bh[4];
                ldsm4(bh, sst + GB_OFF + bo);
#pragma unroll
                for (int half = 0; half < 2; half++)
#pragma unroll
                    for (int mt = 0; mt < 2; mt++)
                        mma_f16(c[mt][2 * p + half], ah[mt], bh + 2 * half);
            }
        }
        __syncthreads();
        if (kc + 2 < 8) load_stage(kc & 1, kc + 2);
        CP_COMMIT();
    }

#pragma unroll
    for (int mt = 0; mt < 2; mt++) {
        int row = m0 + wm * 32 + mt * 16 + (lane >> 2);
#pragma unroll
        for (int nt = 0; nt < 4; nt++) {
            int col = n0 + wn * 32 + nt * 8 + (lane & 3) * 2;
            float v0, v1, v2, v3;
            if (bias_row) {
                float br0 = bias[row], br1 = bias[row + 8];
                v0 = c[mt][nt][0] + br0; v1 = c[mt][nt][1] + br0;
                v2 = c[mt][nt][2] + br1; v3 = c[mt][nt][3] + br1;
            } else {
                float bc0 = bias[col], bc1 = bias[col + 1];
                v0 = c[mt][nt][0] + bc0; v1 = c[mt][nt][1] + bc1;
                v2 = c[mt][nt][2] + bc0; v3 = c[mt][nt][3] + bc1;
            }
            *(uint32_t*)(Ch + (size_t)row * ldc + col) = packh2(v0, v1);
            *(uint32_t*)(Ch + (size_t)(row + 8) * ldc + col) = packh2(v2, v3);
        }
    }
}

// ---------------- generic tiled SGEMM (small fp32 matrices) -------------------------
__global__ void sgemm_bias(const float* __restrict__ A, const float* __restrict__ B,
                           const float* __restrict__ bias, float* __restrict__ C,
                           int M, int N, int K) {
    __shared__ float As[16][68];
    __shared__ float Bs[16][68];
    const int tid = threadIdx.x;
    const int tn = tid & 15, tm = tid >> 4;
    const int m0 = blockIdx.y * 64, n0 = blockIdx.x * 64;

    float acc[4][4];
#pragma unroll
    for (int i = 0; i < 4; i++)
#pragma unroll
        for (int j = 0; j < 4; j++) acc[i][j] = 0.f;

    for (int k0 = 0; k0 < K; k0 += 16) {
        {
            int m = tid >> 2;
            int kq = (tid & 3) * 4;
            float4 v = *(const float4*)(A + (size_t)(m0 + m) * K + k0 + kq);
            As[kq + 0][m] = v.x; As[kq + 1][m] = v.y;
            As[kq + 2][m] = v.z; As[kq + 3][m] = v.w;
        }
        {
            int kk = tid >> 4;
            int nq = (tid & 15) * 4;
            *(float4*)&Bs[kk][nq] = *(const float4*)(B + (size_t)(k0 + kk) * N + n0 + nq);
        }
        __syncthreads();
#pragma unroll
        for (int kk = 0; kk < 16; kk++) {
            float4 a = *(const float4*)&As[kk][tm * 4];
            float4 b = *(const float4*)&Bs[kk][tn * 4];
            float av[4] = {a.x, a.y, a.z, a.w};
            float bv[4] = {b.x, b.y, b.z, b.w};
#pragma unroll
            for (int i = 0; i < 4; i++)
#pragma unroll
                for (int j = 0; j < 4; j++) acc[i][j] += av[i] * bv[j];
        }
        __syncthreads();
    }
#pragma unroll
    for (int i = 0; i < 4; i++) {
        size_t m = (size_t)(m0 + tm * 4 + i);
#pragma unroll
        for (int j = 0; j < 4; j++) {
            int n = n0 + tn * 4 + j;
            C[m * N + n] = acc[i][j] + bias[n];
        }
    }
}

// ---------------- tensor-core flash attention (fp16), stage 1, key-split ------------
#define FL_RB  144
#define FL_Q  0
#define FL_K  9216
#define FL_V  18432
#define FL_MK 27648
#define FL_SMEM (27648 + 256)

__global__ __launch_bounds__(128)
void flash1_tc(const __half* __restrict__ Qh, const __half* __restrict__ Kh,
               const __half* __restrict__ Vth, const int* __restrict__ mask,
               float* __restrict__ Op, float* __restrict__ Mp, float* __restrict__ Lp) {
    extern __shared__ char sb[];
    const uint32_t fb = smem_u32(sb);
    float* mk = (float*)(sb + FL_MK);
    const int tid = threadIdx.x, lane = tid & 31, w = tid >> 5;
    const int qt = blockIdx.x & 3, ks = blockIdx.x >> 2;
    const int h = blockIdx.y, b = blockIdx.z;
    const int k_begin = ks * KPER;
    const int k_end = min(k_begin + KPER, NKEY);

    for (int idx = tid; idx < 512; idx += 128) {
        int row = idx >> 3, j = idx & 7;
        size_t g = (size_t)(qt * 64 + row) * DOUT + h * HD + j * 8;
        *(uint4*)(sb + FL_Q + row * FL_RB + j * 16) = *(const uint4*)(Qh + g);
    }
    __syncthreads();

    uint32_t qf[4][4];
    {
        uint32_t base = (uint32_t)(w * 16 + (lane >> 2)) * FL_RB + (lane & 3) * 4;
#pragma unroll
        for (int kd = 0; kd < 4; kd++) {
            uint32_t o0 = base + kd * 32;
            qf[kd][0] = *(const uint32_t*)(sb + FL_Q + o0);
            qf[kd][1] = *(const uint32_t*)(sb + FL_Q + o0 + 8 * FL_RB);
            qf[kd][2] = *(const uint32_t*)(sb + FL_Q + o0 + 16);
            qf[kd][3] = *(const uint32_t*)(sb + FL_Q + o0 + 8 * FL_RB + 16);
        }
    }

    float m0 = -1e30f, m1 = -1e30f, lsum0 = 0.f, lsum1 = 0.f;
    float o[8][4];
#pragma unroll
    for (int nt = 0; nt < 8; nt++)
#pragma unroll
        for (int i = 0; i < 4; i++) o[nt][i] = 0.f;

    const uint32_t brow_lane = (uint32_t)(((lane >> 4) << 3) + (lane & 7));
    const uint32_t bcol16 = (uint32_t)(((lane >> 3) & 1) * 16);

    for (int kc = k_begin; kc < k_end; kc += 64) {
        int rem = min(64, k_end - kc);
        int pm = 0;
        if (tid < 64) {
            pm = (tid >= rem) || (mask[(size_t)b * NKEY + kc + tid] != 0);
            mk[tid] = pm ? 1.f : 0.f;
        }
        if (__syncthreads_count(pm) == 64) continue;

        for (int idx = tid; idx < 512; idx += 128) {
            int row = idx >> 3, j = idx & 7;
            uint4 zk = make_uint4(0, 0, 0, 0);
            if (row < rem) {
                size_t g = (size_t)(b * NKEY + kc + row) * DOUT + h * HD + j * 8;
                zk = *(const uint4*)(Kh + g);
            }
            *(uint4*)(sb + FL_K + row * FL_RB + j * 16) = zk;
            size_t gv = (size_t)(h * HD + row) * (BATCH * NKEY) + (size_t)b * NKEY + kc + j * 8;
            *(uint4*)(sb + FL_V + row * FL_RB + j * 16) = *(const uint4*)(Vth + gv);
        }
        __syncthreads();

        // ---- S = Q K^T (fp16 single-pass) ----
        float s[8][4];
#pragma unroll
        for (int nt = 0; nt < 8; nt++)
#pragma unroll
            for (int i = 0; i < 4; i++) s[nt][i] = 0.f;
#pragma unroll
        for (int kd = 0; kd < 4; kd++) {
            uint32_t cb = kd * 32 + bcol16;
#pragma unroll
            for (int pp = 0; pp < 2; pp++) {
                uint32_t bo0 = ((uint32_t)((2 * pp) * 16) + brow_lane) * FL_RB + cb;
                uint32_t bo1 = ((uint32_t)((2 * pp + 1) * 16) + brow_lane) * FL_RB + cb;
                uint32_t bh0[4], bh1[4];
                ldsm4(bh0, fb + FL_K + bo0);
                ldsm4(bh1, fb + FL_K + bo1);
                mma_f16(s[4 * pp + 0], qf[kd], bh0);
                mma_f16(s[4 * pp + 1], qf[kd], bh0 + 2);
                mma_f16(s[4 * pp + 2], qf[kd], bh1);
                mma_f16(s[4 * pp + 3], qf[kd], bh1 + 2);
            }
        }

        // ---- mask + scale + online softmax ----
        float mx0 = -1e30f, mx1 = -1e30f;
#pragma unroll
        for (int nt = 0; nt < 8; nt++) {
            int c0 = nt * 8 + (lane & 3) * 2;
            float2 mm = *(const float2*)&mk[c0];
            s[nt][0] = (mm.x > 0.f) ? -1e30f : s[nt][0] * SCALE;
            s[nt][1] = (mm.y > 0.f) ? -1e30f : s[nt][1] * SCALE;
            s[nt][2] = (mm.x > 0.f) ? -1e30f : s[nt][2] * SCALE;
            s[nt][3] = (mm.y > 0.f) ? -1e30f : s[nt][3] * SCALE;
            mx0 = fmaxf(mx0, fmaxf(s[nt][0], s[nt][1]));
            mx1 = fmaxf(mx1, fmaxf(s[nt][2], s[nt][3]));
        }
        mx0 = fmaxf(mx0, __shfl_xor_sync(0xffffffffu, mx0, 1));
        mx0 = fmaxf(mx0, __shfl_xor_sync(0xffffffffu, mx0, 2));
        mx1 = fmaxf(mx1, __shfl_xor_sync(0xffffffffu, mx1, 1));
        mx1 = fmaxf(mx1, __shfl_xor_sync(0xffffffffu, mx1, 2));
        float mn0 = fmaxf(m0, mx0), mn1 = fmaxf(m1, mx1);
        float a0 = __expf(m0 - mn0), a1 = __expf(m1 - mn1);
        m0 = mn0; m1 = mn1;
        float rs0 = 0.f, rs1 = 0.f;
#pragma unroll
        for (int nt = 0; nt < 8; nt++) {
            s[nt][0] = __expf(s[nt][0] - mn0);
            s[nt][1] = __expf(s[nt][1] - mn0);
            s[nt][2] = __expf(s[nt][2] - mn1);
            s[nt][3] = __expf(s[nt][3] - mn1);
            rs0 += s[nt][0] + s[nt][1];
            rs1 += s[nt][2] + s[nt][3];
        }
        rs0 += __shfl_xor_sync(0xffffffffu, rs0, 1);
        rs0 += __shfl_xor_sync(0xffffffffu, rs0, 2);
        rs1 += __shfl_xor_sync(0xffffffffu, rs1, 1);
        rs1 += __shfl_xor_sync(0xffffffffu, rs1, 2);
        lsum0 = lsum0 * a0 + rs0;
        lsum1 = lsum1 * a1 + rs1;
#pragma unroll
        for (int nt = 0; nt < 8; nt++) {
            o[nt][0] *= a0; o[nt][1] *= a0; o[nt][2] *= a1; o[nt][3] *= a1;
        }

        // ---- O += P V (fp16 single-pass) ----
#pragma unroll
        for (int k2 = 0; k2 < 4; k2++) {
            uint32_t ap[4];
            ap[0] = packh2(s[2 * k2][0],     s[2 * k2][1]);
            ap[1] = packh2(s[2 * k2][2],     s[2 * k2][3]);
            ap[2] = packh2(s[2 * k2 + 1][0], s[2 * k2 + 1][1]);
            ap[3] = packh2(s[2 * k2 + 1][2], s[2 * k2 + 1][3]);
            uint32_t cb = k2 * 32 + bcol16;
#pragma unroll
            for (int pp = 0; pp < 2; pp++) {
                uint32_t vo0 = ((uint32_t)((2 * pp) * 16) + brow_lane) * FL_RB + cb;
                uint32_t vo1 = ((uint32_t)((2 * pp + 1) * 16) + brow_lane) * FL_RB + cb;
                uint32_t vh0[4], vh1[4];
                ldsm4(vh0, fb + FL_V + vo0);
                ldsm4(vh1, fb + FL_V + vo1);
                mma_f16(o[4 * pp + 0], ap, vh0);
                mma_f16(o[4 * pp + 1], ap, vh0 + 2);
                mma_f16(o[4 * pp + 2], ap, vh1);
                mma_f16(o[4 * pp + 3], ap, vh1 + 2);
            }
        }
    }

    {
        int r = w * 16 + (lane >> 2);
        int q0 = qt * 64 + r, q1 = q0 + 8;
        size_t ob = ((size_t)ks * BATCH + b) * NQ1;
#pragma unroll
        for (int nt = 0; nt < 8; nt++) {
            int col = h * HD + nt * 8 + (lane & 3) * 2;
            *(float2*)&Op[(ob + q0) * DOUT + col] = make_float2(o[nt][0], o[nt][1]);
            *(float2*)&Op[(ob + q1) * DOUT + col] = make_float2(o[nt][2], o[nt][3]);
        }
        if ((lane & 3) == 0) {
            size_t mi0 = (ob + q0) * NH + h, mi1 = (ob + q1) * NH + h;
            Mp[mi0] = m0; Lp[mi0] = lsum0;
            Mp[mi1] = m1; Lp[mi1] = lsum1;
        }
    }
}

// ---------------- merge key-split partials ------------------------------------------
__global__ void flash_merge(const float* __restrict__ Op, const float* __restrict__ Mp,
                            const float* __restrict__ Lp, float* __restrict__ O) {
    const int q = blockIdx.x, h = blockIdx.y, b = blockIdx.z;
    const int tid = threadIdx.x;   // 64
    __shared__ float sm_[KSPLIT], sl_[KSPLIT];
    if (tid < KSPLIT) {
        size_t mi = (((size_t)tid * BATCH + b) * NQ1 + q) * NH + h;
        sm_[tid] = Mp[mi];
        sl_[tid] = Lp[mi];
    }
    __syncthreads();
    float M = sm_[0];
#pragma unroll
    for (int s = 1; s < KSPLIT; s++) M = fmaxf(M, sm_[s]);
    float num = 0.f, den = 0.f;
#pragma unroll
    for (int s = 0; s < KSPLIT; s++) {
        float w = __expf(sm_[s] - M);
        den += w * sl_[s];
        num += w * Op[(((size_t)s * BATCH + b) * NQ1 + q) * DOUT + h * HD + tid];
    }
    O[((size_t)(b * NQ1) + q) * DOUT + h * HD + tid] = num / den;
}

// ---------------- stage-2 attention -------------------------------------------------
__global__ void attn2_kernel(const float* __restrict__ Q2, const float* __restrict__ K2,
                             const float* __restrict__ V2, float* __restrict__ P,
                             float* __restrict__ O2) {
    const int q = blockIdx.x, h = blockIdx.y, b = blockIdx.z;
    __shared__ float qs[HD];
    __shared__ float ps[NQ1];
    __shared__ float red[4];
    const int tid = threadIdx.x;   // 128

    if (tid < HD) qs[tid] = Q2[(size_t)q * DOUT + h * HD + tid];
    __syncthreads();

    float sv[2];
#pragma unroll
    for (int r = 0; r < 2; r++) {
        int k = tid + r * 128;
        const float* kr = K2 + ((size_t)(b * NQ1 + k)) * DOUT + h * HD;
        float s = 0.f;
#pragma unroll 8
        for (int d = 0; d < HD; d++) s += qs[d] * kr[d];
        sv[r] = s * SCALE;
    }
    float mx = fmaxf(sv[0], sv[1]);
#pragma unroll
    for (int off = 16; off > 0; off >>= 1) mx = fmaxf(mx, __shfl_xor_sync(0xffffffffu, mx, off));
    if ((tid & 31) == 0) red[tid >> 5] = mx;
    __syncthreads();
    mx = fmaxf(fmaxf(red[0], red[1]), fmaxf(red[2], red[3]));

    float e0 = __expf(sv[0] - mx), e1 = __expf(sv[1] - mx);
    float sum = e0 + e1;
#pragma unroll
    for (int off = 16; off > 0; off >>= 1) sum += __shfl_xor_sync(0xffffffffu, sum, off);
    __syncthreads();
    if ((tid & 31) == 0) red[tid >> 5] = sum;
    __syncthreads();
    sum = red[0] + red[1] + red[2] + red[3];
    float inv = 1.f / sum;

    ps[tid] = e0 * inv; ps[tid + 128] = e1 * inv;
    float* Prow = P + (((size_t)(b * NH + h) * NQ2 + q) * NQ1);
    Prow[tid] = e0 * inv; Prow[tid + 128] = e1 * inv;
    __syncthreads();

    if (tid < HD) {
        float acc = 0.f;
        for (int k = 0; k < NQ1; k++)
            acc += ps[k] * V2[((size_t)(b * NQ1 + k)) * DOUT + h * HD + tid];
        O2[((size_t)(b * NQ2 + q)) * DOUT + h * HD + tid] = acc;
    }
}

__global__ void attn_mean_kernel(const float* __restrict__ P, float* __restrict__ out) {
    int idx = blockIdx.x * blockDim.x + threadIdx.x;
    if (idx >= BATCH * NQ2 * NQ1) return;
    int k = idx % NQ1;
    int q = (idx / NQ1) % NQ2;
    int b = idx / (NQ1 * NQ2);
    float s = 0.f;
#pragma unroll
    for (int h = 0; h < NH; h++)
        s += P[(((size_t)(b * NH + h) * NQ2) + q) * NQ1 + k];
    out[idx] = s * (1.f / NH);
}

__global__ void ln_kernel(const float* __restrict__ X, const float* __restrict__ g,
                          const float* __restrict__ be, float* __restrict__ Y) {
    const int row = blockIdx.x;
    const float* x = X + (size_t)row * DOUT;
    float* y = Y + (size_t)row * DOUT;
    const int tid = threadIdx.x;   // 128
    float s = 0.f, s2 = 0.f;
#pragma unroll
    for (int i = tid; i < DOUT; i += 128) { float v = x[i]; s += v; s2 += v * v; }
    __shared__ float rs[4], rs2[4];
#pragma unroll
    for (int off = 16; off > 0; off >>= 1) {
        s  += __shfl_xor_sync(0xffffffffu, s,  off);
        s2 += __shfl_xor_sync(0xffffffffu, s2, off);
    }
    if ((tid & 31) == 0) { rs[tid >> 5] = s; rs2[tid >> 5] = s2; }
    __syncthreads();
    s  = rs[0]  + rs[1]  + rs[2]  + rs[3];
    s2 = rs2[0] + rs2[1] + rs2[2] + rs2[3];
    float mu  = s * (1.f / DOUT);
    float var = s2 * (1.f / DOUT) - mu * mu;
    float inv = rsqrtf(var + LN_EPS);
#pragma unroll
    for (int i = tid; i < DOUT; i += 128)
        y[i] = (x[i] - mu) * inv * g[i] + be[i];
}

// ---------------- host ----------------------------------------------------------------
extern "C" void kernel_launch(void* const* d_in, const int* in_sizes, int n_in,
                              void* d_out, int out_size) {
    const float* X    = (const float*)d_in[0];
    const int*   mask = (const int*)d_in[1];
    const float* q1   = (const float*)d_in[2];
    const float* Wq1  = (const float*)d_in[3];
    const float* bq1  = (const float*)d_in[4];
    const float* Wk1  = (const float*)d_in[5];
    const float* bk1  = (const float*)d_in[6];
    const float* Wv1  = (const float*)d_in[7];
    const float* bv1  = (const float*)d_in[8];
    const float* Wo1  = (const float*)d_in[9];
    const float* bo1  = (const float*)d_in[10];
    const float* g1   = (const float*)d_in[11];
    const float* be1  = (const float*)d_in[12];
    const float* q2   = (const float*)d_in[13];
    const float* Wq2  = (const float*)d_in[14];
    const float* bq2  = (const float*)d_in[15];
    const float* Wk2  = (const float*)d_in[16];
    const float* bk2  = (const float*)d_in[17];
    const float* Wv2  = (const float*)d_in[18];
    const float* bv2  = (const float*)d_in[19];
    const float* Wo2  = (const float*)d_in[20];
    const float* bo2  = (const float*)d_in[21];
    const float* g2   = (const float*)d_in[22];
    const float* be2  = (const float*)d_in[23];

    float* out = (float*)d_out;
    float* out_attn = out + BATCH * NQ2 * DOUT;

    float *Q1, *O1, *I1, *Q2, *K2, *V2, *P2, *O2, *X2, *Opart, *Mpart, *Lpart;
    uint4 *Xh, *WtK, *WtV, *K16, *Vt16, *Q1h;
    cudaGetSymbolAddress((void**)&Q1, g_Q1);
    cudaGetSymbolAddress((void**)&O1, g_O1);
    cudaGetSymbolAddress((void**)&I1, g_I1);
    cudaGetSymbolAddress((void**)&Q2, g_Q2);
    cudaGetSymbolAddress((void**)&K2, g_K2);
    cudaGetSymbolAddress((void**)&V2, g_V2);
    cudaGetSymbolAddress((void**)&P2, g_P2);
    cudaGetSymbolAddress((void**)&O2, g_O2);
    cudaGetSymbolAddress((void**)&X2, g_X2);
    cudaGetSymbolAddress((void**)&Opart, g_Opart);
    cudaGetSymbolAddress((void**)&Mpart, g_Mpart);
    cudaGetSymbolAddress((void**)&Lpart, g_Lpart);
    cudaGetSymbolAddress((void**)&Xh, g_Xh);
    cudaGetSymbolAddress((void**)&WtK, g_WtK);
    cudaGetSymbolAddress((void**)&WtV, g_WtV);
    cudaGetSymbolAddress((void**)&K16, g_K16);
    cudaGetSymbolAddress((void**)&Vt16, g_Vt16);
    cudaGetSymbolAddress((void**)&Q1h, g_Q1h);

    cudaFuncSetAttribute(gemm_mma_fp16, cudaFuncAttributeMaxDynamicSharedMemorySize, SM_GEMM_TOTAL);
    cudaFuncSetAttribute(flash1_tc, cudaFuncAttributeMaxDynamicSharedMemorySize, FL_SMEM);

    // ---- stage 1 ----
    const int n4 = BATCH * NKEY * DIN / 4;
    conv_half<<<(n4 + 255) / 256, 256>>>((const float4*)X, (uint2*)Xh, n4);
    conv_wt_h<<<(DOUT * DIN) / 256, 256>>>(Wk1, (__half*)WtK);
    conv_wt_h<<<(DOUT * DIN) / 256, 256>>>(Wv1, (__half*)WtV);

    // K[token][d] = X @ WtK^T + bk1(col): M = 80000, N = 512
    gemm_mma_fp16<<<dim3(8, BATCH * NKEY / 128), 256, SM_GEMM_TOTAL>>>(
        Xh, WtK, bk1, 0, (__half*)K16, DOUT);
    // Vt[d][token] = WtV @ X^T + bv1(row): M = 512, N = 80000
    gemm_mma_fp16<<<dim3(BATCH * NKEY / 64, 4), 256, SM_GEMM_TOTAL>>>(
        WtV, Xh, bv1, 1, (__half*)Vt16, BATCH * NKEY);

    sgemm_bias<<<dim3(8, 4), 256>>>(q1, Wq1, bq1, Q1, NQ1, DOUT, DOUT);
    q_half<<<(NQ1 * DOUT + 255) / 256, 256>>>(Q1, (__half*)Q1h, NQ1 * DOUT);

    flash1_tc<<<dim3(4 * KSPLIT, NH, BATCH), 128, FL_SMEM>>>(
        (const __half*)Q1h, (const __half*)K16, (const __half*)Vt16,
        mask, Opart, Mpart, Lpart);
    flash_merge<<<dim3(NQ1, NH, BATCH), 64>>>(Opart, Mpart, Lpart, O1);

    sgemm_bias<<<dim3(8, 16), 256>>>(O1, Wo1, bo1, I1, BATCH * NQ1, DOUT, DOUT);
    ln_kernel<<<BATCH * NQ1, 128>>>(I1, g1, be1, I1);

    // ---- stage 2 ----
    sgemm_bias<<<dim3(8, 1),  256>>>(q2, Wq2, bq2, Q2, NQ2, DOUT, DOUT);
    sgemm_bias<<<dim3(8, 16), 256>>>(I1, Wk2, bk2, K2, BATCH * NQ1, DOUT, DOUT);
    sgemm_bias<<<dim3(8, 16), 256>>>(I1, Wv2, bv2, V2, BATCH * NQ1, DOUT, DOUT);
    attn2_kernel<<<dim3(NQ2, NH, BATCH), 128>>>(Q2, K2, V2, P2, O2);
    attn_mean_kernel<<<(BATCH * NQ2 * NQ1 + 255) / 256, 256>>>(P2, out_attn);
    sgemm_bias<<<dim3(8, 4), 256>>>(O2, Wo2, bo2, X2, NQ2 * BATCH, DOUT, DOUT);
    ln_kernel<<<BATCH * NQ2, 128>>>(X2, g2, be2, out);
}

// round 17
// speedup vs baseline: 1.5514x; 1.0725x over previous
#include <cuda_runtime.h>
#include <cuda_fp16.h>
#include <cstdint>
#include <cstddef>

// Problem constants
#define DOUT 512
#define NH   8
#define HD   64
#define NQ1  256
#define NQ2  64
#define BATCH 4
#define NKEY 20000
#define DIN  256
#define LN_EPS 1e-5f
#define SCALE 0.125f
#define KSPLIT 16
#define KPER   1280

// ---------------- scratch (device globals; no allocations allowed) ----------------
__device__ float g_Q1[NQ1 * DOUT];
__device__ float g_O1[BATCH * NQ1 * DOUT];
__device__ float g_I1[BATCH * NQ1 * DOUT];
__device__ float g_Q2[NQ2 * DOUT];
__device__ float g_K2[BATCH * NQ1 * DOUT];
__device__ float g_V2[BATCH * NQ1 * DOUT];
__device__ float g_P2[BATCH * NH * NQ2 * NQ1];
__device__ float g_O2[BATCH * NQ2 * DOUT];
__device__ float g_X2[BATCH * NQ2 * DOUT];
__device__ uint4 g_Xh[BATCH * NKEY * DIN * 2 / 16];     // fp16
__device__ uint4 g_WtK[DOUT * DIN * 2 / 16];            // fp16 [512][256]
__device__ uint4 g_WtV[DOUT * DIN * 2 / 16];
__device__ uint4 g_K16[BATCH * NKEY * DOUT * 2 / 16];   // fp16 K [token][d]
__device__ uint4 g_Vt16[(DOUT * BATCH * NKEY * 2 + 512) / 16]; // fp16 V [d][token]
__device__ uint4 g_Q1h[NQ1 * DOUT * 2 / 16];
__device__ float g_Opart[KSPLIT * BATCH * NQ1 * DOUT];
__device__ float g_Mpart[KSPLIT * BATCH * NQ1 * NH];
__device__ float g_Lpart[KSPLIT * BATCH * NQ1 * NH];

// ---------------- helpers ------------------------------------------------------------
__device__ __forceinline__ void mma_f16(float* c, const uint32_t* a, const uint32_t* b) {
    asm volatile(
        "mma.sync.aligned.m16n8k16.row.col.f32.f16.f16.f32 "
        "{%0,%1,%2,%3}, {%4,%5,%6,%7}, {%8,%9}, {%0,%1,%2,%3};"
        : "+f"(c[0]), "+f"(c[1]), "+f"(c[2]), "+f"(c[3])
        : "r"(a[0]), "r"(a[1]), "r"(a[2]), "r"(a[3]), "r"(b[0]), "r"(b[1]));
}
__device__ __forceinline__ void ldsm4(uint32_t* r, uint32_t addr) {
    asm volatile("ldmatrix.sync.aligned.m8n8.x4.shared.b16 {%0,%1,%2,%3}, [%4];"
        : "=r"(r[0]), "=r"(r[1]), "=r"(r[2]), "=r"(r[3]) : "r"(addr));
}
__device__ __forceinline__ uint32_t smem_u32(const void* p) {
    uint32_t a;
    asm("{ .reg .u64 t; cvta.to.shared.u64 t, %1; cvt.u32.u64 %0, t; }" : "=r"(a) : "l"(p));
    return a;
}
__device__ __forceinline__ void cp16(uint32_t dst, const void* src) {
    asm volatile("cp.async.cg.shared.global [%0], [%1], 16;" :: "r"(dst), "l"(src));
}
#define CP_COMMIT() asm volatile("cp.async.commit_group;" ::: "memory")
#define CP_WAIT1()  asm volatile("cp.async.wait_group 1;" ::: "memory")

__device__ __forceinline__ uint32_t packh2(float f0, float f1) {
    __half2 h = __floats2half2_rn(f0, f1);
    return *(uint32_t*)&h;
}

// ---------------- fp32 -> fp16 conversions ------------------------------------------
__global__ void conv_half(const float4* __restrict__ X, uint2* __restrict__ H, int n4) {
    int idx = blockIdx.x * blockDim.x + threadIdx.x;
    if (idx >= n4) return;
    float4 v = X[idx];
    H[idx] = make_uint2(packh2(v.x, v.y), packh2(v.z, v.w));
}

__global__ void conv_wt_h(const float* __restrict__ W, __half* __restrict__ Wt) {
    int idx = blockIdx.x * blockDim.x + threadIdx.x;
    int n = idx >> 8, k = idx & 255;
    Wt[idx] = __float2half_rn(W[k * DOUT + n]);
}

__global__ void q_half(const float* __restrict__ Q, __half* __restrict__ Qh, int n) {
    int idx = blockIdx.x * blockDim.x + threadIdx.x;
    if (idx >= n) return;
    Qh[idx] = __float2half_rn(Q[idx]);
}

// ---------------- HMMA fp16 GEMM: CTA 128x128, BK=32, 2-stage cp.async --------------
#define GROWB 80u
#define GB_OFF 10240u
#define GSTG  20480u
#define SM_GEMM_TOTAL (2 * 20480)

__global__ __launch_bounds__(256, 2)
void gemm_mma_fp16(const uint4* __restrict__ Ah4, const uint4* __restrict__ Bh4,
                   const float* __restrict__ bias, int bias_row,
                   __half* __restrict__ Ch, int ldc) {
    extern __shared__ char smc[];
    const uint32_t sbase = smem_u32(smc);
    const int tid = threadIdx.x, lane = tid & 31, w = tid >> 5;
    const int wm = w & 3, wn = w >> 2;           // warp tile 32x64
    const int m0 = blockIdx.y * 128, n0 = blockIdx.x * 128;

    float c[2][8][4];
#pragma unroll
    for (int mt = 0; mt < 2; mt++)
#pragma unroll
        for (int nt = 0; nt < 8; nt++)
#pragma unroll
            for (int i = 0; i < 4; i++) c[mt][nt][i] = 0.f;

    // stage loader: A 512 + B 512 chunks, 4 per thread
    auto load_stage = [&](int s, int kc) {
#pragma unroll
        for (int i = tid; i < 1024; i += 256) {
            uint32_t dst;
            size_t gi;
            const uint4* src;
            if (i < 512) {
                int r = i >> 2, j = i & 3;
                dst = sbase + (uint32_t)s * GSTG + (uint32_t)r * GROWB + (uint32_t)j * 16u;
                gi = (size_t)(m0 + r) * 32 + kc * 4 + j;
                src = Ah4;
            } else {
                int i2 = i - 512;
                int r = i2 >> 2, j = i2 & 3;
                dst = sbase + (uint32_t)s * GSTG + GB_OFF + (uint32_t)r * GROWB + (uint32_t)j * 16u;
                gi = (size_t)(n0 + r) * 32 + kc * 4 + j;
                src = Bh4;
            }
            cp16(dst, src + gi);
        }
    };

    load_stage(0, 0); CP_COMMIT();
    load_stage(1, 1); CP_COMMIT();

    for (int kc = 0; kc < 8; kc++) {
        CP_WAIT1();
        __syncthreads();
        const uint32_t sst = sbase + (uint32_t)(kc & 1) * GSTG;

#pragma unroll
        for (int ks = 0; ks < 2; ks++) {
            const uint32_t kb = (uint32_t)ks * 32u;
            uint32_t ah[2][4];
#pragma unroll
            for (int mt = 0; mt < 2; mt++) {
                uint32_t arow = (uint32_t)(wm * 32 + mt * 16 + (lane & 15));
                uint32_t ao = arow * GROWB + kb + (uint32_t)((lane >> 4) * 16);
                ldsm4(ah[mt], sst + ao);
            }
#pragma unroll
            for (int p = 0; p < 4; p++) {
                uint32_t brow = (uint32_t)(wn * 64 + p * 16 + ((lane >> 4) << 3) + (lane & 7));
                uint32_t bo = brow * GROWB + kb + (uint32_t)(((lane >> 3) & 1) * 16);
                uint32_t bh[4];
                ldsm4(bh, sst + GB_OFF + bo);
#pragma unroll
                for (int half = 0; half < 2; half++)
#pragma unroll
                    for (int mt = 0; mt < 2; mt++)
                        mma_f16(c[mt][2 * p + half], ah[mt], bh + 2 * half);
            }
        }
        __syncthreads();
        if (kc + 2 < 8) load_stage(kc & 1, kc + 2);
        CP_COMMIT();
    }

#pragma unroll
    for (int mt = 0; mt < 2; mt++) {
        int row = m0 + wm * 32 + mt * 16 + (lane >> 2);
#pragma unroll
        for (int nt = 0; nt < 8; nt++) {
            int col = n0 + wn * 64 + nt * 8 + (lane & 3) * 2;
            float v0, v1, v2, v3;
            if (bias_row) {
                float br0 = bias[row], br1 = bias[row + 8];
                v0 = c[mt][nt][0] + br0; v1 = c[mt][nt][1] + br0;
                v2 = c[mt][nt][2] + br1; v3 = c[mt][nt][3] + br1;
            } else {
                float bc0 = bias[col], bc1 = bias[col + 1];
                v0 = c[mt][nt][0] + bc0; v1 = c[mt][nt][1] + bc1;
                v2 = c[mt][nt][2] + bc0; v3 = c[mt][nt][3] + bc1;
            }
            *(uint32_t*)(Ch + (size_t)row * ldc + col) = packh2(v0, v1);
            *(uint32_t*)(Ch + (size_t)(row + 8) * ldc + col) = packh2(v2, v3);
        }
    }
}

// ---------------- generic tiled SGEMM (small fp32 matrices) -------------------------
__global__ void sgemm_bias(const float* __restrict__ A, const float* __restrict__ B,
                           const float* __restrict__ bias, float* __restrict__ C,
                           int M, int N, int K) {
    __shared__ float As[16][68];
    __shared__ float Bs[16][68];
    const int tid = threadIdx.x;
    const int tn = tid & 15, tm = tid >> 4;
    const int m0 = blockIdx.y * 64, n0 = blockIdx.x * 64;

    float acc[4][4];
#pragma unroll
    for (int i = 0; i < 4; i++)
#pragma unroll
        for (int j = 0; j < 4; j++) acc[i][j] = 0.f;

    for (int k0 = 0; k0 < K; k0 += 16) {
        {
            int m = tid >> 2;
            int kq = (tid & 3) * 4;
            float4 v = *(const float4*)(A + (size_t)(m0 + m) * K + k0 + kq);
            As[kq + 0][m] = v.x; As[kq + 1][m] = v.y;
            As[kq + 2][m] = v.z; As[kq + 3][m] = v.w;
        }
        {
            int kk = tid >> 4;
            int nq = (tid & 15) * 4;
            *(float4*)&Bs[kk][nq] = *(const float4*)(B + (size_t)(k0 + kk) * N + n0 + nq);
        }
        __syncthreads();
#pragma unroll
        for (int kk = 0; kk < 16; kk++) {
            float4 a = *(const float4*)&As[kk][tm * 4];
            float4 b = *(const float4*)&Bs[kk][tn * 4];
            float av[4] = {a.x, a.y, a.z, a.w};
            float bv[4] = {b.x, b.y, b.z, b.w};
#pragma unroll
            for (int i = 0; i < 4; i++)
#pragma unroll
                for (int j = 0; j < 4; j++) acc[i][j] += av[i] * bv[j];
        }
        __syncthreads();
    }
#pragma unroll
    for (int i = 0; i < 4; i++) {
        size_t m = (size_t)(m0 + tm * 4 + i);
#pragma unroll
        for (int j = 0; j < 4; j++) {
            int n = n0 + tn * 4 + j;
            C[m * N + n] = acc[i][j] + bias[n];
        }
    }
}

// ---------------- tensor-core flash attention (fp16), all 256 queries per CTA -------
// grid (KSPLIT, NH, BATCH), 512 threads (16 warps). Warp w owns q rows w*16..w*16+15.
#define FL_RB  144
#define FL_Q  0
#define FL_K  36864
#define FL_V  46080
#define FL_MK 55296
#define FL_SMEM (55296 + 256)

__global__ __launch_bounds__(512)
void flash1_tc(const __half* __restrict__ Qh, const __half* __restrict__ Kh,
               const __half* __restrict__ Vth, const int* __restrict__ mask,
               float* __restrict__ Op, float* __restrict__ Mp, float* __restrict__ Lp) {
    extern __shared__ char sb[];
    const uint32_t fb = smem_u32(sb);
    float* mk = (float*)(sb + FL_MK);
    const int tid = threadIdx.x, lane = tid & 31, w = tid >> 5;
    const int ks = blockIdx.x, h = blockIdx.y, b = blockIdx.z;
    const int k_begin = ks * KPER;
    const int k_end = min(k_begin + KPER, NKEY);

    // load all 256 Q rows for this head
    for (int idx = tid; idx < 2048; idx += 512) {
        int row = idx >> 3, j = idx & 7;
        size_t g = (size_t)row * DOUT + h * HD + j * 8;
        *(uint4*)(sb + FL_Q + row * FL_RB + j * 16) = *(const uint4*)(Qh + g);
    }
    __syncthreads();

    uint32_t qf[4][4];
    {
        uint32_t base = (uint32_t)(w * 16 + (lane >> 2)) * FL_RB + (lane & 3) * 4;
#pragma unroll
        for (int kd = 0; kd < 4; kd++) {
            uint32_t o0 = base + kd * 32;
            qf[kd][0] = *(const uint32_t*)(sb + FL_Q + o0);
            qf[kd][1] = *(const uint32_t*)(sb + FL_Q + o0 + 8 * FL_RB);
            qf[kd][2] = *(const uint32_t*)(sb + FL_Q + o0 + 16);
            qf[kd][3] = *(const uint32_t*)(sb + FL_Q + o0 + 8 * FL_RB + 16);
        }
    }

    float m0 = -1e30f, m1 = -1e30f, lsum0 = 0.f, lsum1 = 0.f;
    float o[8][4];
#pragma unroll
    for (int nt = 0; nt < 8; nt++)
#pragma unroll
        for (int i = 0; i < 4; i++) o[nt][i] = 0.f;

    const uint32_t brow_lane = (uint32_t)(((lane >> 4) << 3) + (lane & 7));
    const uint32_t bcol16 = (uint32_t)(((lane >> 3) & 1) * 16);

    for (int kc = k_begin; kc < k_end; kc += 64) {
        int rem = min(64, k_end - kc);
        int pm = 0;
        if (tid < 64) {
            pm = (tid >= rem) || (mask[(size_t)b * NKEY + kc + tid] != 0);
            mk[tid] = pm ? 1.f : 0.f;
        }
        if (__syncthreads_count(pm) == 512) continue;  // tid>=64 contribute 0; 64 masked -> count==512? no
        // NOTE: __syncthreads_count counts over ALL threads; only tid<64 can be nonzero.
        // Full chunk masked <=> count == 64.
        // (re-evaluate with explicit check below)
        if (mk[0] >= 0.f) { /* no-op to keep mk live */ }
        {
            // recompute skip decision from shared mask (count stored via ballot in mk[64]?)
        }
        // cheap skip: if all 64 mk entries are 1 -> skip (one warp scans)
        // Use warp 0 to OR-reduce
        __shared__ int s_skip;
        if (tid < 64) {
            // none
        }
        if (tid == 0) {
            int allm = 1;
#pragma unroll
            for (int t = 0; t < 64; t += 4) {
                float4 mm = *(const float4*)&mk[t];
                if (mm.x == 0.f || mm.y == 0.f || mm.z == 0.f || mm.w == 0.f) { allm = 0; break; }
            }
            s_skip = allm;
        }
        __syncthreads();
        if (s_skip) continue;

        for (int idx = tid; idx < 1024; idx += 512) {
            if (idx < 512) {
                int row = idx >> 3, j = idx & 7;
                uint4 zk = make_uint4(0, 0, 0, 0);
                if (row < rem) {
                    size_t g = (size_t)(b * NKEY + kc + row) * DOUT + h * HD + j * 8;
                    zk = *(const uint4*)(Kh + g);
                }
                *(uint4*)(sb + FL_K + row * FL_RB + j * 16) = zk;
            } else {
                int i2 = idx - 512;
                int row = i2 >> 3, j = i2 & 7;
                size_t gv = (size_t)(h * HD + row) * (BATCH * NKEY) + (size_t)b * NKEY + kc + j * 8;
                *(uint4*)(sb + FL_V + row * FL_RB + j * 16) = *(const uint4*)(Vth + gv);
            }
        }
        __syncthreads();

        // ---- S = Q K^T ----
        float s[8][4];
#pragma unroll
        for (int nt = 0; nt < 8; nt++)
#pragma unroll
            for (int i = 0; i < 4; i++) s[nt][i] = 0.f;
#pragma unroll
        for (int kd = 0; kd < 4; kd++) {
            uint32_t cb = kd * 32 + bcol16;
#pragma unroll
            for (int pp = 0; pp < 2; pp++) {
                uint32_t bo0 = ((uint32_t)((2 * pp) * 16) + brow_lane) * FL_RB + cb;
                uint32_t bo1 = ((uint32_t)((2 * pp + 1) * 16) + brow_lane) * FL_RB + cb;
                uint32_t bh0[4], bh1[4];
                ldsm4(bh0, fb + FL_K + bo0);
                ldsm4(bh1, fb + FL_K + bo1);
                mma_f16(s[4 * pp + 0], qf[kd], bh0);
                mma_f16(s[4 * pp + 1], qf[kd], bh0 + 2);
                mma_f16(s[4 * pp + 2], qf[kd], bh1);
                mma_f16(s[4 * pp + 3], qf[kd], bh1 + 2);
            }
        }

        // ---- mask + scale + online softmax ----
        float mx0 = -1e30f, mx1 = -1e30f;
#pragma unroll
        for (int nt = 0; nt < 8; nt++) {
            int c0 = nt * 8 + (lane & 3) * 2;
            float2 mm = *(const float2*)&mk[c0];
            s[nt][0] = (mm.x > 0.f) ? -1e30f : s[nt][0] * SCALE;
            s[nt][1] = (mm.y > 0.f) ? -1e30f : s[nt][1] * SCALE;
            s[nt][2] = (mm.x > 0.f) ? -1e30f : s[nt][2] * SCALE;
            s[nt][3] = (mm.y > 0.f) ? -1e30f : s[nt][3] * SCALE;
            mx0 = fmaxf(mx0, fmaxf(s[nt][0], s[nt][1]));
            mx1 = fmaxf(mx1, fmaxf(s[nt][2], s[nt][3]));
        }
        mx0 = fmaxf(mx0, __shfl_xor_sync(0xffffffffu, mx0, 1));
        mx0 = fmaxf(mx0, __shfl_xor_sync(0xffffffffu, mx0, 2));
        mx1 = fmaxf(mx1, __shfl_xor_sync(0xffffffffu, mx1, 1));
        mx1 = fmaxf(mx1, __shfl_xor_sync(0xffffffffu, mx1, 2));
        float mn0 = fmaxf(m0, mx0), mn1 = fmaxf(m1, mx1);
        float a0 = __expf(m0 - mn0), a1 = __expf(m1 - mn1);
        m0 = mn0; m1 = mn1;
        float rs0 = 0.f, rs1 = 0.f;
#pragma unroll
        for (int nt = 0; nt < 8; nt++) {
            s[nt][0] = __expf(s[nt][0] - mn0);
            s[nt][1] = __expf(s[nt][1] - mn0);
            s[nt][2] = __expf(s[nt][2] - mn1);
            s[nt][3] = __expf(s[nt][3] - mn1);
            rs0 += s[nt][0] + s[nt][1];
            rs1 += s[nt][2] + s[nt][3];
        }
        rs0 += __shfl_xor_sync(0xffffffffu, rs0, 1);
        rs0 += __shfl_xor_sync(0xffffffffu, rs0, 2);
        rs1 += __shfl_xor_sync(0xffffffffu, rs1, 1);
        rs1 += __shfl_xor_sync(0xffffffffu, rs1, 2);
        lsum0 = lsum0 * a0 + rs0;
        lsum1 = lsum1 * a1 + rs1;
#pragma unroll
        for (int nt = 0; nt < 8; nt++) {
            o[nt][0] *= a0; o[nt][1] *= a0; o[nt][2] *= a1; o[nt][3] *= a1;
        }

        // ---- O += P V ----
#pragma unroll
        for (int k2 = 0; k2 < 4; k2++) {
            uint32_t ap[4];
            ap[0] = packh2(s[2 * k2][0],     s[2 * k2][1]);
            ap[1] = packh2(s[2 * k2][2],     s[2 * k2][3]);
            ap[2] = packh2(s[2 * k2 + 1][0], s[2 * k2 + 1][1]);
            ap[3] = packh2(s[2 * k2 + 1][2], s[2 * k2 + 1][3]);
            uint32_t cb = k2 * 32 + bcol16;
#pragma unroll
            for (int pp = 0; pp < 2; pp++) {
                uint32_t vo0 = ((uint32_t)((2 * pp) * 16) + brow_lane) * FL_RB + cb;
                uint32_t vo1 = ((uint32_t)((2 * pp + 1) * 16) + brow_lane) * FL_RB + cb;
                uint32_t vh0[4], vh1[4];
                ldsm4(vh0, fb + FL_V + vo0);
                ldsm4(vh1, fb + FL_V + vo1);
                mma_f16(o[4 * pp + 0], ap, vh0);
                mma_f16(o[4 * pp + 1], ap, vh0 + 2);
                mma_f16(o[4 * pp + 2], ap, vh1);
                mma_f16(o[4 * pp + 3], ap, vh1 + 2);
            }
        }
    }

    {
        int q0 = w * 16 + (lane >> 2), q1 = q0 + 8;
        size_t ob = ((size_t)ks * BATCH + b) * NQ1;
#pragma unroll
        for (int nt = 0; nt < 8; nt++) {
            int col = h * HD + nt * 8 + (lane & 3) * 2;
            *(float2*)&Op[(ob + q0) * DOUT + col] = make_float2(o[nt][0], o[nt][1]);
            *(float2*)&Op[(ob + q1) * DOUT + col] = make_float2(o[nt][2], o[nt][3]);
        }
        if ((lane & 3) == 0) {
            size_t mi0 = (ob + q0) * NH + h, mi1 = (ob + q1) * NH + h;
            Mp[mi0] = m0; Lp[mi0] = lsum0;
            Mp[mi1] = m1; Lp[mi1] = lsum1;
        }
    }
}

// ---------------- merge key-split partials ------------------------------------------
__global__ void flash_merge(const float* __restrict__ Op, const float* __restrict__ Mp,
                            const float* __restrict__ Lp, float* __restrict__ O) {
    const int q = blockIdx.x, h = blockIdx.y, b = blockIdx.z;
    const int tid = threadIdx.x;   // 64
    __shared__ float sm_[KSPLIT], sl_[KSPLIT];
    if (tid < KSPLIT) {
        size_t mi = (((size_t)tid * BATCH + b) * NQ1 + q) * NH + h;
        sm_[tid] = Mp[mi];
        sl_[tid] = Lp[mi];
    }
    __syncthreads();
    float M = sm_[0];
#pragma unroll
    for (int s = 1; s < KSPLIT; s++) M = fmaxf(M, sm_[s]);
    float num = 0.f, den = 0.f;
#pragma unroll
    for (int s = 0; s < KSPLIT; s++) {
        float w = __expf(sm_[s] - M);
        den += w * sl_[s];
        num += w * Op[(((size_t)s * BATCH + b) * NQ1 + q) * DOUT + h * HD + tid];
    }
    O[((size_t)(b * NQ1) + q) * DOUT + h * HD + tid] = num / den;
}

// ---------------- stage-2 attention -------------------------------------------------
__global__ void attn2_kernel(const float* __restrict__ Q2, const float* __restrict__ K2,
                             const float* __restrict__ V2, float* __restrict__ P,
                             float* __restrict__ O2) {
    const int q = blockIdx.x, h = blockIdx.y, b = blockIdx.z;
    __shared__ float qs[HD];
    __shared__ float ps[NQ1];
    __shared__ float red[4];
    const int tid = threadIdx.x;   // 128

    if (tid < HD) qs[tid] = Q2[(size_t)q * DOUT + h * HD + tid];
    __syncthreads();

    float sv[2];
#pragma unroll
    for (int r = 0; r < 2; r++) {
        int k = tid + r * 128;
        const float* kr = K2 + ((size_t)(b * NQ1 + k)) * DOUT + h * HD;
        float s = 0.f;
#pragma unroll 8
        for (int d = 0; d < HD; d++) s += qs[d] * kr[d];
        sv[r] = s * SCALE;
    }
    float mx = fmaxf(sv[0], sv[1]);
#pragma unroll
    for (int off = 16; off > 0; off >>= 1) mx = fmaxf(mx, __shfl_xor_sync(0xffffffffu, mx, off));
    if ((tid & 31) == 0) red[tid >> 5] = mx;
    __syncthreads();
    mx = fmaxf(fmaxf(red[0], red[1]), fmaxf(red[2], red[3]));

    float e0 = __expf(sv[0] - mx), e1 = __expf(sv[1] - mx);
    float sum = e0 + e1;
#pragma unroll
    for (int off = 16; off > 0; off >>= 1) sum += __shfl_xor_sync(0xffffffffu, sum, off);
    __syncthreads();
    if ((tid & 31) == 0) red[tid >> 5] = sum;
    __syncthreads();
    sum = red[0] + red[1] + red[2] + red[3];
    float inv = 1.f / sum;

    ps[tid] = e0 * inv; ps[tid + 128] = e1 * inv;
    float* Prow = P + (((size_t)(b * NH + h) * NQ2 + q) * NQ1);
    Prow[tid] = e0 * inv; Prow[tid + 128] = e1 * inv;
    __syncthreads();

    if (tid < HD) {
        float acc = 0.f;
        for (int k = 0; k < NQ1; k++)
            acc += ps[k] * V2[((size_t)(b * NQ1 + k)) * DOUT + h * HD + tid];
        O2[((size_t)(b * NQ2 + q)) * DOUT + h * HD + tid] = acc;
    }
}

__global__ void attn_mean_kernel(const float* __restrict__ P, float* __restrict__ out) {
    int idx = blockIdx.x * blockDim.x + threadIdx.x;
    if (idx >= BATCH * NQ2 * NQ1) return;
    int k = idx % NQ1;
    int q = (idx / NQ1) % NQ2;
    int b = idx / (NQ1 * NQ2);
    float s = 0.f;
#pragma unroll
    for (int h = 0; h < NH; h++)
        s += P[(((size_t)(b * NH + h) * NQ2) + q) * NQ1 + k];
    out[idx] = s * (1.f / NH);
}

__global__ void ln_kernel(const float* __restrict__ X, const float* __restrict__ g,
                          const float* __restrict__ be, float* __restrict__ Y) {
    const int row = blockIdx.x;
    const float* x = X + (size_t)row * DOUT;
    float* y = Y + (size_t)row * DOUT;
    const int tid = threadIdx.x;   // 128
    float s = 0.f, s2 = 0.f;
#pragma unroll
    for (int i = tid; i < DOUT; i += 128) { float v = x[i]; s += v; s2 += v * v; }
    __shared__ float rs[4], rs2[4];
#pragma unroll
    for (int off = 16; off > 0; off >>= 1) {
        s  += __shfl_xor_sync(0xffffffffu, s,  off);
        s2 += __shfl_xor_sync(0xffffffffu, s2, off);
    }
    if ((tid & 31) == 0) { rs[tid >> 5] = s; rs2[tid >> 5] = s2; }
    __syncthreads();
    s  = rs[0]  + rs[1]  + rs[2]  + rs[3];
    s2 = rs2[0] + rs2[1] + rs2[2] + rs2[3];
    float mu  = s * (1.f / DOUT);
    float var = s2 * (1.f / DOUT) - mu * mu;
    float inv = rsqrtf(var + LN_EPS);
#pragma unroll
    for (int i = tid; i < DOUT; i += 128)
        y[i] = (x[i] - mu) * inv * g[i] + be[i];
}

// ---------------- host ----------------------------------------------------------------
extern "C" void kernel_launch(void* const* d_in, const int* in_sizes, int n_in,
                              void* d_out, int out_size) {
    const float* X    = (const float*)d_in[0];
    const int*   mask = (const int*)d_in[1];
    const float* q1   = (const float*)d_in[2];
    const float* Wq1  = (const float*)d_in[3];
    const float* bq1  = (const float*)d_in[4];
    const float* Wk1  = (const float*)d_in[5];
    const float* bk1  = (const float*)d_in[6];
    const float* Wv1  = (const float*)d_in[7];
    const float* bv1  = (const float*)d_in[8];
    const float* Wo1  = (const float*)d_in[9];
    const float* bo1  = (const float*)d_in[10];
    const float* g1   = (const float*)d_in[11];
    const float* be1  = (const float*)d_in[12];
    const float* q2   = (const float*)d_in[13];
    const float* Wq2  = (const float*)d_in[14];
    const float* bq2  = (const float*)d_in[15];
    const float* Wk2  = (const float*)d_in[16];
    const float* bk2  = (const float*)d_in[17];
    const float* Wv2  = (const float*)d_in[18];
    const float* bv2  = (const float*)d_in[19];
    const float* Wo2  = (const float*)d_in[20];
    const float* bo2  = (const float*)d_in[21];
    const float* g2   = (const float*)d_in[22];
    const float* be2  = (const float*)d_in[23];

    float* out = (float*)d_out;
    float* out_attn = out + BATCH * NQ2 * DOUT;

    float *Q1, *O1, *I1, *Q2, *K2, *V2, *P2, *O2, *X2, *Opart, *Mpart, *Lpart;
    uint4 *Xh, *WtK, *WtV, *K16, *Vt16, *Q1h;
    cudaGetSymbolAddress((void**)&Q1, g_Q1);
    cudaGetSymbolAddress((void**)&O1, g_O1);
    cudaGetSymbolAddress((void**)&I1, g_I1);
    cudaGetSymbolAddress((void**)&Q2, g_Q2);
    cudaGetSymbolAddress((void**)&K2, g_K2);
    cudaGetSymbolAddress((void**)&V2, g_V2);
    cudaGetSymbolAddress((void**)&P2, g_P2);
    cudaGetSymbolAddress((void**)&O2, g_O2);
    cudaGetSymbolAddress((void**)&X2, g_X2);
    cudaGetSymbolAddress((void**)&Opart, g_Opart);
    cudaGetSymbolAddress((void**)&Mpart, g_Mpart);
    cudaGetSymbolAddress((void**)&Lpart, g_Lpart);
    cudaGetSymbolAddress((void**)&Xh, g_Xh);
    cudaGetSymbolAddress((void**)&WtK, g_WtK);
    cudaGetSymbolAddress((void**)&WtV, g_WtV);
    cudaGetSymbolAddress((void**)&K16, g_K16);
    cudaGetSymbolAddress((void**)&Vt16, g_Vt16);
    cudaGetSymbolAddress((void**)&Q1h, g_Q1h);

    cudaFuncSetAttribute(gemm_mma_fp16, cudaFuncAttributeMaxDynamicSharedMemorySize, SM_GEMM_TOTAL);
    cudaFuncSetAttribute(flash1_tc, cudaFuncAttributeMaxDynamicSharedMemorySize, FL_SMEM);

    // ---- stage 1 ----
    const int n4 = BATCH * NKEY * DIN / 4;
    conv_half<<<(n4 + 255) / 256, 256>>>((const float4*)X, (uint2*)Xh, n4);
    conv_wt_h<<<(DOUT * DIN) / 256, 256>>>(Wk1, (__half*)WtK);
    conv_wt_h<<<(DOUT * DIN) / 256, 256>>>(Wv1, (__half*)WtV);

    // K[token][d] = X @ WtK^T + bk1(col): M = 80000, N = 512
    gemm_mma_fp16<<<dim3(4, BATCH * NKEY / 128), 256, SM_GEMM_TOTAL>>>(
        Xh, WtK, bk1, 0, (__half*)K16, DOUT);
    // Vt[d][token] = WtV @ X^T + bv1(row): M = 512, N = 80000
    gemm_mma_fp16<<<dim3(BATCH * NKEY / 128, 4), 256, SM_GEMM_TOTAL>>>(
        WtV, Xh, bv1, 1, (__half*)Vt16, BATCH * NKEY);

    sgemm_bias<<<dim3(8, 4), 256>>>(q1, Wq1, bq1, Q1, NQ1, DOUT, DOUT);
    q_half<<<(NQ1 * DOUT + 255) / 256, 256>>>(Q1, (__half*)Q1h, NQ1 * DOUT);

    flash1_tc<<<dim3(KSPLIT, NH, BATCH), 512, FL_SMEM>>>(
        (const __half*)Q1h, (const __half*)K16, (const __half*)Vt16,
        mask, Opart, Mpart, Lpart);
    flash_merge<<<dim3(NQ1, NH, BATCH), 64>>>(Opart, Mpart, Lpart, O1);

    sgemm_bias<<<dim3(8, 16), 256>>>(O1, Wo1, bo1, I1, BATCH * NQ1, DOUT, DOUT);
    ln_kernel<<<BATCH * NQ1, 128>>>(I1, g1, be1, I1);

    // ---- stage 2 ----
    sgemm_bias<<<dim3(8, 1),  256>>>(q2, Wq2, bq2, Q2, NQ2, DOUT, DOUT);
    sgemm_bias<<<dim3(8, 16), 256>>>(I1, Wk2, bk2, K2, BATCH * NQ1, DOUT, DOUT);
    sgemm_bias<<<dim3(8, 16), 256>>>(I1, Wv2, bv2, V2, BATCH * NQ1, DOUT, DOUT);
    attn2_kernel<<<dim3(NQ2, NH, BATCH), 128>>>(Q2, K2, V2, P2, O2);
    attn_mean_kernel<<<(BATCH * NQ2 * NQ1 + 255) / 256, 256>>>(P2, out_attn);
    sgemm_bias<<<dim3(8, 4), 256>>>(O2, Wo2, bo2, X2, NQ2 * BATCH, DOUT, DOUT);
    ln_kernel<<<BATCH * NQ2, 128>>>(X2, g2, be2, out);
}